// round 10
// baseline (speedup 1.0000x reference)
#include <cuda_runtime.h>
#include <math.h>

#define BB    2
#define MM    2048
#define DIMF  512
#define HEADS 8
#define DHD   64
#define INNER 512
#define QKVD  1536
#define ROWS  (BB*MM)       // 4096

__device__ float g_normed[ROWS * DIMF];
__device__ float g_qkv[ROWS * QKVD];
__device__ float g_outpre[ROWS * INNER];

__device__ __forceinline__ void mma_tf32(float c[4],
                                         unsigned a0, unsigned a1, unsigned a2, unsigned a3,
                                         unsigned b0, unsigned b1) {
    asm volatile(
        "mma.sync.aligned.m16n8k8.row.col.f32.tf32.tf32.f32 "
        "{%0,%1,%2,%3}, {%4,%5,%6,%7}, {%8,%9}, {%0,%1,%2,%3};\n"
        : "+f"(c[0]), "+f"(c[1]), "+f"(c[2]), "+f"(c[3])
        : "r"(a0), "r"(a1), "r"(a2), "r"(a3), "r"(b0), "r"(b1));
}
__device__ __forceinline__ unsigned f2u(float x) { return __float_as_uint(x); }
__device__ __forceinline__ float ex2(float x) {
    float y; asm("ex2.approx.ftz.f32 %0, %1;" : "=f"(y) : "f"(x)); return y;
}

__device__ __forceinline__ void cp16(float* s, const float* g) {
    unsigned sa = (unsigned)__cvta_generic_to_shared(s);
    asm volatile("cp.async.ca.shared.global [%0], [%1], 16;\n" :: "r"(sa), "l"(g));
}
__device__ __forceinline__ void cp4(float* s, const float* g) {
    unsigned sa = (unsigned)__cvta_generic_to_shared(s);
    asm volatile("cp.async.ca.shared.global [%0], [%1], 4;\n" :: "r"(sa), "l"(g));
}
#define CP_COMMIT() asm volatile("cp.async.commit_group;\n" ::: "memory")
#define CP_WAIT(n)  asm volatile("cp.async.wait_group %0;\n" :: "n"(n) : "memory")

// ---------------------------------------------------------------- LayerNorm
__global__ void ln_kernel(const float* __restrict__ x,
                          const float* __restrict__ gamma,
                          const float* __restrict__ beta) {
    int row = blockIdx.x;
    int t = threadIdx.x;
    const float* xr = x + (size_t)row * DIMF;
    float v0 = xr[t], v1 = xr[t + 256];
    float s = v0 + v1, ss = v0 * v0 + v1 * v1;
    #pragma unroll
    for (int o = 16; o > 0; o >>= 1) {
        s  += __shfl_xor_sync(0xffffffffu, s, o);
        ss += __shfl_xor_sync(0xffffffffu, ss, o);
    }
    __shared__ float ws[8], wss[8];
    if ((t & 31) == 0) { ws[t >> 5] = s; wss[t >> 5] = ss; }
    __syncthreads();
    float S = 0.f, SS = 0.f;
    #pragma unroll
    for (int i = 0; i < 8; i++) { S += ws[i]; SS += wss[i]; }
    float mean = S * (1.0f / DIMF);
    float var  = SS * (1.0f / DIMF) - mean * mean;
    float inv  = rsqrtf(var + 1e-5f);
    float* o = g_normed + (size_t)row * DIMF;
    o[t]       = (v0 - mean) * inv * gamma[t]       + beta[t];
    o[t + 256] = (v1 - mean) * inv * gamma[t + 256] + beta[t + 256];
}

// ---------------------------------------------------------------- GEMM0: 256x128 CTA tile, 64x64 warp tiles
// g_normed[4096,512] @ w_qkv[512,1536] -> g_qkv
__device__ __forceinline__ void g0_load(const float* __restrict__ A,
                                        const float* __restrict__ Bmat,
                                        float* Asd, float* Bsd,
                                        int m0, int n0, int k0, int t) {
    #pragma unroll
    for (int i = 0; i < 8; i++) {
        int lin = t + i * 256;
        int r = lin >> 3, c = (lin & 7) * 4;
        cp16(&Asd[r * 36 + c], &A[(size_t)(m0 + r) * 512 + k0 + c]);
    }
    #pragma unroll
    for (int i = 0; i < 4; i++) {
        int lin = t + i * 256;
        int r = lin >> 5, c = (lin & 31) * 4;
        cp16(&Bsd[r * 136 + c], &Bmat[(size_t)(k0 + r) * QKVD + n0 + c]);
    }
}

__global__ __launch_bounds__(256, 1) void gemm0_tf32(const float* __restrict__ Bmat) {
    const float* A = g_normed;
    float* C = g_qkv;
    extern __shared__ float smem[];
    float* As0 = smem;
    float* As1 = smem + 256 * 36;
    float* Bs0 = smem + 2 * 256 * 36;
    float* Bs1 = Bs0 + 32 * 136;

    int m0 = blockIdx.y * 256, n0 = blockIdx.x * 128;
    int t = threadIdx.x;
    int w = t >> 5, lane = t & 31;
    int wm = w >> 1, wn = w & 1;          // warp grid 4x2, warp tile 64x64
    int g = lane >> 2, tq = lane & 3;

    float acc[4][8][4] = {};

    g0_load(A, Bmat, As0, Bs0, m0, n0, 0, t);
    CP_COMMIT();

    for (int kc = 0; kc < 16; kc++) {
        float* Asc = (kc & 1) ? As1 : As0;
        float* Bsc = (kc & 1) ? Bs1 : Bs0;
        if (kc < 15) {
            float* Asn = (kc & 1) ? As0 : As1;
            float* Bsn = (kc & 1) ? Bs0 : Bs1;
            g0_load(A, Bmat, Asn, Bsn, m0, n0, (kc + 1) * 32, t);
            CP_COMMIT();
            CP_WAIT(1);
        } else {
            CP_WAIT(0);
        }
        __syncthreads();
        #pragma unroll
        for (int kk = 0; kk < 4; kk++) {
            unsigned a[4][4];
            #pragma unroll
            for (int mt = 0; mt < 4; mt++) {
                int br = 64 * wm + 16 * mt;
                a[mt][0] = f2u(Asc[(br + g)     * 36 + 8 * kk + tq]);
                a[mt][1] = f2u(Asc[(br + 8 + g) * 36 + 8 * kk + tq]);
                a[mt][2] = f2u(Asc[(br + g)     * 36 + 8 * kk + tq + 4]);
                a[mt][3] = f2u(Asc[(br + 8 + g) * 36 + 8 * kk + tq + 4]);
            }
            #pragma unroll
            for (int nt = 0; nt < 8; nt++) {
                int bc = 64 * wn + 8 * nt + g;
                unsigned b0 = f2u(Bsc[(8 * kk + tq)     * 136 + bc]);
                unsigned b1 = f2u(Bsc[(8 * kk + tq + 4) * 136 + bc]);
                #pragma unroll
                for (int mt = 0; mt < 4; mt++)
                    mma_tf32(acc[mt][nt], a[mt][0], a[mt][1], a[mt][2], a[mt][3], b0, b1);
            }
        }
        __syncthreads();
    }

    #pragma unroll
    for (int mt = 0; mt < 4; mt++) {
        #pragma unroll
        for (int rr = 0; rr < 2; rr++) {
            int row = m0 + 64 * wm + 16 * mt + g + 8 * rr;
            #pragma unroll
            for (int nt = 0; nt < 8; nt++) {
                int col = n0 + 64 * wn + 8 * nt + 2 * tq;
                *(float2*)&C[(size_t)row * QKVD + col] =
                    make_float2(acc[mt][nt][2 * rr], acc[mt][nt][2 * rr + 1]);
            }
        }
    }
}

// ---------------------------------------------------------------- GEMM1: 128x64 tile (unchanged)
// g_outpre[4096,512] @ w_out[512,512] + bias, GELU, + residual -> out
__device__ __forceinline__ void g1_load(const float* __restrict__ A,
                                        const float* __restrict__ Bmat,
                                        float* Asd, float* Bsd,
                                        int m0, int n0, int k0, int t) {
    #pragma unroll
    for (int i = 0; i < 4; i++) {
        int lin = t + i * 256;
        int r = lin >> 3, c = (lin & 7) * 4;
        cp16(&Asd[r * 36 + c], &A[(size_t)(m0 + r) * 512 + k0 + c]);
    }
    #pragma unroll
    for (int i = 0; i < 2; i++) {
        int lin = t + i * 256;
        int r = lin >> 4, c = (lin & 15) * 4;
        cp16(&Bsd[r * 72 + c], &Bmat[(size_t)(k0 + r) * DIMF + n0 + c]);
    }
}

__global__ __launch_bounds__(256, 2) void gemm1_tf32(const float* __restrict__ Bmat,
                          const float* __restrict__ bias,
                          const float* __restrict__ resid,
                          float* __restrict__ C) {
    const float* A = g_outpre;
    extern __shared__ float smem[];
    float* As0 = smem;
    float* As1 = smem + 128 * 36;
    float* Bs0 = smem + 2 * 128 * 36;
    float* Bs1 = Bs0 + 32 * 72;

    int m0 = blockIdx.y * 128, n0 = blockIdx.x * 64;
    int t = threadIdx.x;
    int w = t >> 5, lane = t & 31;
    int wm = w >> 1, wn = w & 1;          // warp tile 32x32
    int g = lane >> 2, tq = lane & 3;

    float acc[2][4][4] = {};

    g1_load(A, Bmat, As0, Bs0, m0, n0, 0, t);
    CP_COMMIT();

    for (int kc = 0; kc < 16; kc++) {
        float* Asc = (kc & 1) ? As1 : As0;
        float* Bsc = (kc & 1) ? Bs1 : Bs0;
        if (kc < 15) {
            float* Asn = (kc & 1) ? As0 : As1;
            float* Bsn = (kc & 1) ? Bs0 : Bs1;
            g1_load(A, Bmat, Asn, Bsn, m0, n0, (kc + 1) * 32, t);
            CP_COMMIT();
            CP_WAIT(1);
        } else {
            CP_WAIT(0);
        }
        __syncthreads();
        #pragma unroll
        for (int kk = 0; kk < 4; kk++) {
            unsigned a[2][4];
            #pragma unroll
            for (int mt = 0; mt < 2; mt++) {
                int br = 32 * wm + 16 * mt;
                a[mt][0] = f2u(Asc[(br + g)     * 36 + 8 * kk + tq]);
                a[mt][1] = f2u(Asc[(br + 8 + g) * 36 + 8 * kk + tq]);
                a[mt][2] = f2u(Asc[(br + g)     * 36 + 8 * kk + tq + 4]);
                a[mt][3] = f2u(Asc[(br + 8 + g) * 36 + 8 * kk + tq + 4]);
            }
            #pragma unroll
            for (int nt = 0; nt < 4; nt++) {
                int bc = 32 * wn + 8 * nt + g;
                unsigned b0 = f2u(Bsc[(8 * kk + tq)     * 72 + bc]);
                unsigned b1 = f2u(Bsc[(8 * kk + tq + 4) * 72 + bc]);
                mma_tf32(acc[0][nt], a[0][0], a[0][1], a[0][2], a[0][3], b0, b1);
                mma_tf32(acc[1][nt], a[1][0], a[1][1], a[1][2], a[1][3], b0, b1);
            }
        }
        __syncthreads();
    }

    #pragma unroll
    for (int mt = 0; mt < 2; mt++) {
        #pragma unroll
        for (int rr = 0; rr < 2; rr++) {
            int row = m0 + 32 * wm + 16 * mt + g + 8 * rr;
            #pragma unroll
            for (int nt = 0; nt < 4; nt++) {
                int col = n0 + 32 * wn + 8 * nt + 2 * tq;
                float x0 = acc[mt][nt][2 * rr + 0] + bias[col];
                float x1 = acc[mt][nt][2 * rr + 1] + bias[col + 1];
                x0 = 0.5f * x0 * (1.0f + erff(x0 * 0.70710678118654752f));
                x1 = 0.5f * x1 * (1.0f + erff(x1 * 0.70710678118654752f));
                x0 += resid[(size_t)row * DIMF + col];
                x1 += resid[(size_t)row * DIMF + col + 1];
                *(float2*)&C[(size_t)row * DIMF + col] = make_float2(x0, x1);
            }
        }
    }
}

// ---------------------------------------------------------------- tf32 flash attention + xyz agg
// 128 threads (4 warps), 128-query tile, 32 rows/warp (2 m-subtiles -> B-frag reuse),
// 64-key tiles, 2-stage cp.async, no-max softmax (exp2, log2e folded into Q scale).
#define KSTR 68
#define VSTR 72
#define PSTR 68
#define ATTN_SMEM ((2*64*KSTR + 2*64*VSTR + 128*PSTR) * 4)

__device__ __forceinline__ void attn_load_stage(const float* __restrict__ kbase,
                                                const float* __restrict__ vbase,
                                                const float* __restrict__ xyzb,
                                                int j0, float* kb, float* vb, int t) {
    int r = t >> 1, c = (t & 1) * 32;
    const float* gk = kbase + (size_t)(j0 + r) * QKVD + c;
    const float* gv = vbase + (size_t)(j0 + r) * QKVD + c;
    #pragma unroll
    for (int u = 0; u < 8; u++) {
        cp16(&kb[r * KSTR + c + u * 4], gk + u * 4);
        cp16(&vb[r * VSTR + c + u * 4], gv + u * 4);
    }
    if (t < 64) {
        const float* gx = xyzb + (size_t)(j0 + t) * 3;
        cp4(&vb[t * VSTR + 64], gx);
        cp4(&vb[t * VSTR + 65], gx + 1);
        cp4(&vb[t * VSTR + 66], gx + 2);
    }
}

__global__ __launch_bounds__(128, 2) void attn_kernel(const float* __restrict__ xyzs,
                                                      const float* __restrict__ w_sp) {
    extern __shared__ float sm[];
    float* kbuf0 = sm;
    float* kbuf1 = sm + 64 * KSTR;
    float* vbuf0 = sm + 2 * 64 * KSTR;
    float* vbuf1 = vbuf0 + 64 * VSTR;
    float* pb    = vbuf0 + 2 * 64 * VSTR;

    int bh = blockIdx.y;
    int b = bh >> 3, h = bh & 7;
    int i0 = blockIdx.x * 128;
    int t = threadIdx.x;
    int w = t >> 5, lane = t & 31;
    int g = lane >> 2, tq = lane & 3;
    int prw = 32 * w;

    const float* qkvb = g_qkv + (size_t)b * MM * QKVD;
    const float* xyzb = xyzs + (size_t)b * MM * 3;
    const float* kbase = qkvb + INNER + h * DHD;
    const float* vbase = qkvb + 2 * INNER + h * DHD;

    // zero pad cols 67..71 in both V buffers (written once)
    {
        float* vv = ((t < 64) ? vbuf0 : vbuf1) + (t & 63) * VSTR;
        #pragma unroll
        for (int c = 67; c < 72; c++) vv[c] = 0.f;
    }

    attn_load_stage(kbase, vbase, xyzb, 0, kbuf0, vbuf0, t);
    CP_COMMIT();

    // Q fragments for 2 m-subtiles; fold in 0.125 * log2(e) so p = 2^s
    const float QS = 0.125f * 1.4426950408889634f;
    unsigned qf[2][8][4];
    #pragma unroll
    for (int m = 0; m < 2; m++) {
        int rl = i0 + prw + 16 * m + g;
        const float* ql = qkvb + (size_t)rl * QKVD + h * DHD;
        const float* qh = ql + 8 * QKVD;
        #pragma unroll
        for (int k0 = 0; k0 < 8; k0++) {
            qf[m][k0][0] = f2u(ql[8 * k0 + tq]     * QS);
            qf[m][k0][1] = f2u(qh[8 * k0 + tq]     * QS);
            qf[m][k0][2] = f2u(ql[8 * k0 + tq + 4] * QS);
            qf[m][k0][3] = f2u(qh[8 * k0 + tq + 4] * QS);
        }
    }

    float of[2][9][4] = {};
    float l[4] = {0.f, 0.f, 0.f, 0.f};

    for (int jt = 0; jt < 32; jt++) {
        float* kb = (jt & 1) ? kbuf1 : kbuf0;
        float* vb = (jt & 1) ? vbuf1 : vbuf0;
        if (jt < 31) {
            float* kn = (jt & 1) ? kbuf0 : kbuf1;
            float* vn = (jt & 1) ? vbuf0 : vbuf1;
            attn_load_stage(kbase, vbase, xyzb, (jt + 1) * 64, kn, vn, t);
            CP_COMMIT();
            CP_WAIT(1);
        } else {
            CP_WAIT(0);
        }
        __syncthreads();

        // S = Q K^T, exp2 inline per n-tile, write P
        #pragma unroll
        for (int n = 0; n < 8; n++) {
            float s0[4] = {}, s1[4] = {};
            const float* kbp = &kb[(8 * n + g) * KSTR];
            #pragma unroll
            for (int k0 = 0; k0 < 8; k0++) {
                unsigned b0 = f2u(kbp[8 * k0 + tq]);
                unsigned b1 = f2u(kbp[8 * k0 + tq + 4]);
                mma_tf32(s0, qf[0][k0][0], qf[0][k0][1], qf[0][k0][2], qf[0][k0][3], b0, b1);
                mma_tf32(s1, qf[1][k0][0], qf[1][k0][1], qf[1][k0][2], qf[1][k0][3], b0, b1);
            }
            #pragma unroll
            for (int r = 0; r < 4; r++) { s0[r] = ex2(s0[r]); s1[r] = ex2(s1[r]); }
            l[0] += s0[0] + s0[1];
            l[1] += s0[2] + s0[3];
            l[2] += s1[0] + s1[1];
            l[3] += s1[2] + s1[3];
            int col = 8 * n + 2 * tq;
            *(float2*)&pb[(prw + g)      * PSTR + col] = make_float2(s0[0], s0[1]);
            *(float2*)&pb[(prw + 8 + g)  * PSTR + col] = make_float2(s0[2], s0[3]);
            *(float2*)&pb[(prw + 16 + g) * PSTR + col] = make_float2(s1[0], s1[1]);
            *(float2*)&pb[(prw + 24 + g) * PSTR + col] = make_float2(s1[2], s1[3]);
        }
        __syncwarp();

        // O += P V_ext (cols 64..66 carry attn@xyz)
        #pragma unroll
        for (int k0 = 0; k0 < 8; k0++) {
            int c0 = 8 * k0 + tq, c1 = c0 + 4;
            unsigned a00 = f2u(pb[(prw + g)      * PSTR + c0]);
            unsigned a01 = f2u(pb[(prw + 8 + g)  * PSTR + c0]);
            unsigned a02 = f2u(pb[(prw + g)      * PSTR + c1]);
            unsigned a03 = f2u(pb[(prw + 8 + g)  * PSTR + c1]);
            unsigned a10 = f2u(pb[(prw + 16 + g) * PSTR + c0]);
            unsigned a11 = f2u(pb[(prw + 24 + g) * PSTR + c0]);
            unsigned a12 = f2u(pb[(prw + 16 + g) * PSTR + c1]);
            unsigned a13 = f2u(pb[(prw + 24 + g) * PSTR + c1]);
            const float* vb0 = &vb[c0 * VSTR + g];
            const float* vb1 = &vb[c1 * VSTR + g];
            #pragma unroll
            for (int n = 0; n < 9; n++) {
                unsigned b0 = f2u(vb0[8 * n]);
                unsigned b1 = f2u(vb1[8 * n]);
                mma_tf32(of[0][n], a00, a01, a02, a03, b0, b1);
                mma_tf32(of[1][n], a10, a11, a12, a13, b0, b1);
            }
        }
        __syncthreads();
    }

    // row-sum reduce across quad
    #pragma unroll
    for (int o = 1; o < 4; o <<= 1) {
        #pragma unroll
        for (int r = 0; r < 4; r++)
            l[r] += __shfl_xor_sync(0xffffffffu, l[r], o);
    }

    // epilogue per m-subtile
    int base = lane & ~3;
    #pragma unroll
    for (int m = 0; m < 2; m++) {
        float invl0 = 1.0f / l[2 * m], invl1 = 1.0f / l[2 * m + 1];
        float ax0l = __shfl_sync(0xffffffffu, of[m][8][0], base + 0);
        float ax1l = __shfl_sync(0xffffffffu, of[m][8][1], base + 0);
        float ax2l = __shfl_sync(0xffffffffu, of[m][8][0], base + 1);
        float ax0h = __shfl_sync(0xffffffffu, of[m][8][2], base + 0);
        float ax1h = __shfl_sync(0xffffffffu, of[m][8][3], base + 0);
        float ax2h = __shfl_sync(0xffffffffu, of[m][8][2], base + 1);

        int rl = i0 + prw + 16 * m + g, rh = rl + 8;
        const float* xl = xyzs + ((size_t)b * MM + rl) * 3;
        const float* xh = xyzs + ((size_t)b * MM + rh) * 3;
        float a0l = ax0l * invl0 - xl[0];
        float a1l = ax1l * invl0 - xl[1];
        float a2l = ax2l * invl0 - xl[2];
        float a0h = ax0h * invl1 - xh[0];
        float a1h = ax1h * invl1 - xh[1];
        float a2h = ax2h * invl1 - xh[2];

        float* orl = g_outpre + ((size_t)b * MM + rl) * INNER + h * DHD;
        float* orh = g_outpre + ((size_t)b * MM + rh) * INNER + h * DHD;
        #pragma unroll
        for (int n = 0; n < 8; n++) {
            int d = 8 * n + 2 * tq;
            float w00 = w_sp[d],       w01 = w_sp[d + 1];
            float w10 = w_sp[64 + d],  w11 = w_sp[64 + d + 1];
            float w20 = w_sp[128 + d], w21 = w_sp[128 + d + 1];
            float o00 = of[m][n][0] * invl0 + a0l * w00 + a1l * w10 + a2l * w20;
            float o01 = of[m][n][1] * invl0 + a0l * w01 + a1l * w11 + a2l * w21;
            float o10 = of[m][n][2] * invl1 + a0h * w00 + a1h * w10 + a2h * w20;
            float o11 = of[m][n][3] * invl1 + a0h * w01 + a1h * w11 + a2h * w21;
            *(float2*)&orl[d] = make_float2(o00, o01);
            *(float2*)&orh[d] = make_float2(o10, o11);
        }
    }
}

// ---------------------------------------------------------------- launch
extern "C" void kernel_launch(void* const* d_in, const int* in_sizes, int n_in,
                              void* d_out, int out_size) {
    const float* xyzs     = (const float*)d_in[0];
    const float* features = (const float*)d_in[1];
    const float* gamma    = (const float*)d_in[2];
    const float* beta     = (const float*)d_in[3];
    const float* w_qkv    = (const float*)d_in[4];
    const float* w_sp     = (const float*)d_in[5];
    const float* w_out    = (const float*)d_in[6];
    const float* b_out    = (const float*)d_in[7];
    float* out = (float*)d_out;

    const int g0_smem = 2 * (256 * 36 + 32 * 136) * 4;   // 108544
    const int g1_smem = 2 * (128 * 36 + 32 * 72) * 4;    // 55296
    cudaFuncSetAttribute(gemm0_tf32, cudaFuncAttributeMaxDynamicSharedMemorySize, g0_smem);
    cudaFuncSetAttribute(gemm1_tf32, cudaFuncAttributeMaxDynamicSharedMemorySize, g1_smem);
    cudaFuncSetAttribute(attn_kernel, cudaFuncAttributeMaxDynamicSharedMemorySize, ATTN_SMEM);

    ln_kernel<<<ROWS, 256>>>(features, gamma, beta);
    gemm0_tf32<<<dim3(QKVD / 128, ROWS / 256), 256, g0_smem>>>(w_qkv);
    attn_kernel<<<dim3(MM / 128, BB * HEADS), 128, ATTN_SMEM>>>(xyzs, w_sp);
    gemm1_tf32<<<dim3(DIMF / 64, ROWS / 128), 256, g1_smem>>>(w_out, b_out, features, out);
}

// round 11
// speedup vs baseline: 1.3915x; 1.3915x over previous
#include <cuda_runtime.h>
#include <math.h>

#define BB    2
#define MM    2048
#define DIMF  512
#define HEADS 8
#define DHD   64
#define INNER 512
#define QKVD  1536
#define ROWS  (BB*MM)       // 4096

__device__ float g_normed[ROWS * DIMF];
__device__ float g_qkv[ROWS * QKVD];
__device__ float g_outpre[ROWS * INNER];

__device__ __forceinline__ void mma_tf32(float c[4],
                                         unsigned a0, unsigned a1, unsigned a2, unsigned a3,
                                         unsigned b0, unsigned b1) {
    asm volatile(
        "mma.sync.aligned.m16n8k8.row.col.f32.tf32.tf32.f32 "
        "{%0,%1,%2,%3}, {%4,%5,%6,%7}, {%8,%9}, {%0,%1,%2,%3};\n"
        : "+f"(c[0]), "+f"(c[1]), "+f"(c[2]), "+f"(c[3])
        : "r"(a0), "r"(a1), "r"(a2), "r"(a3), "r"(b0), "r"(b1));
}
__device__ __forceinline__ unsigned f2u(float x) { return __float_as_uint(x); }
__device__ __forceinline__ float ex2(float x) {
    float y; asm("ex2.approx.ftz.f32 %0, %1;" : "=f"(y) : "f"(x)); return y;
}

__device__ __forceinline__ void cp16(float* s, const float* g) {
    unsigned sa = (unsigned)__cvta_generic_to_shared(s);
    asm volatile("cp.async.ca.shared.global [%0], [%1], 16;\n" :: "r"(sa), "l"(g));
}
__device__ __forceinline__ void cp4(float* s, const float* g) {
    unsigned sa = (unsigned)__cvta_generic_to_shared(s);
    asm volatile("cp.async.ca.shared.global [%0], [%1], 4;\n" :: "r"(sa), "l"(g));
}
#define CP_COMMIT() asm volatile("cp.async.commit_group;\n" ::: "memory")
#define CP_WAIT(n)  asm volatile("cp.async.wait_group %0;\n" :: "n"(n) : "memory")

// ---------------------------------------------------------------- LayerNorm
__global__ void ln_kernel(const float* __restrict__ x,
                          const float* __restrict__ gamma,
                          const float* __restrict__ beta) {
    int row = blockIdx.x;
    int t = threadIdx.x;
    const float* xr = x + (size_t)row * DIMF;
    float v0 = xr[t], v1 = xr[t + 256];
    float s = v0 + v1, ss = v0 * v0 + v1 * v1;
    #pragma unroll
    for (int o = 16; o > 0; o >>= 1) {
        s  += __shfl_xor_sync(0xffffffffu, s, o);
        ss += __shfl_xor_sync(0xffffffffu, ss, o);
    }
    __shared__ float ws[8], wss[8];
    if ((t & 31) == 0) { ws[t >> 5] = s; wss[t >> 5] = ss; }
    __syncthreads();
    float S = 0.f, SS = 0.f;
    #pragma unroll
    for (int i = 0; i < 8; i++) { S += ws[i]; SS += wss[i]; }
    float mean = S * (1.0f / DIMF);
    float var  = SS * (1.0f / DIMF) - mean * mean;
    float inv  = rsqrtf(var + 1e-5f);
    float* o = g_normed + (size_t)row * DIMF;
    o[t]       = (v0 - mean) * inv * gamma[t]       + beta[t];
    o[t + 256] = (v1 - mean) * inv * gamma[t + 256] + beta[t + 256];
}

// ---------------------------------------------------------------- tf32 GEMM, 2-stage cp.async
// tile 128 x BN, k-chunk 32. STAGE0: BN=128 (grid 12x32). STAGE1: BN=64 (grid 8x32).
template <int BN>
__device__ __forceinline__ void gemm_load(const float* __restrict__ A,
                                          const float* __restrict__ Bmat,
                                          float* Asd, float* Bsd,
                                          int m0, int n0, int N, int k0, int t) {
    constexpr int BSTR = BN + 8;
    #pragma unroll
    for (int i = 0; i < 4; i++) {
        int lin = t + i * 256;
        int r = lin >> 3, c = (lin & 7) * 4;
        cp16(&Asd[r * 36 + c], &A[(size_t)(m0 + r) * 512 + k0 + c]);
    }
    #pragma unroll
    for (int i = 0; i < BN / 32; i++) {
        int lin = t + i * 256;
        int r = lin / (BN / 4), c = (lin % (BN / 4)) * 4;
        cp16(&Bsd[r * BSTR + c], &Bmat[(size_t)(k0 + r) * N + n0 + c]);
    }
}

template <int STAGE, int BN>
__global__ __launch_bounds__(256, 2) void gemm_tf32(const float* __restrict__ Bmat,
                          const float* __restrict__ bias,
                          const float* __restrict__ resid,
                          float* __restrict__ CoutP, int N) {
    constexpr int BSTR = BN + 8;
    constexpr int NT = BN / 16;           // n-subtiles per warp
    const float* A = (STAGE == 0) ? g_normed : g_outpre;
    float* C       = (STAGE == 0) ? g_qkv    : CoutP;
    extern __shared__ float smem[];
    float* As0 = smem;
    float* As1 = smem + 128 * 36;
    float* Bs0 = smem + 2 * 128 * 36;
    float* Bs1 = Bs0 + 32 * BSTR;

    int m0 = blockIdx.y * 128, n0 = blockIdx.x * BN;
    int t = threadIdx.x;
    int w = t >> 5, lane = t & 31;
    int wm = w >> 1, wn = w & 1;          // warp grid 4x2; warp tile 32 x BN/2
    int g = lane >> 2, tq = lane & 3;

    float acc[2][NT][4] = {};

    gemm_load<BN>(A, Bmat, As0, Bs0, m0, n0, N, 0, t);
    CP_COMMIT();

    for (int kc = 0; kc < 16; kc++) {
        float* Asc = (kc & 1) ? As1 : As0;
        float* Bsc = (kc & 1) ? Bs1 : Bs0;
        if (kc < 15) {
            float* Asn = (kc & 1) ? As0 : As1;
            float* Bsn = (kc & 1) ? Bs0 : Bs1;
            gemm_load<BN>(A, Bmat, Asn, Bsn, m0, n0, N, (kc + 1) * 32, t);
            CP_COMMIT();
            CP_WAIT(1);
        } else {
            CP_WAIT(0);
        }
        __syncthreads();
        #pragma unroll
        for (int kk = 0; kk < 4; kk++) {
            unsigned a[2][4];
            #pragma unroll
            for (int mt = 0; mt < 2; mt++) {
                int br = 32 * wm + 16 * mt;
                a[mt][0] = f2u(Asc[(br + g)     * 36 + 8 * kk + tq]);
                a[mt][1] = f2u(Asc[(br + 8 + g) * 36 + 8 * kk + tq]);
                a[mt][2] = f2u(Asc[(br + g)     * 36 + 8 * kk + tq + 4]);
                a[mt][3] = f2u(Asc[(br + 8 + g) * 36 + 8 * kk + tq + 4]);
            }
            #pragma unroll
            for (int nt = 0; nt < NT; nt++) {
                int bc = (BN / 2) * wn + 8 * nt + g;
                unsigned b0 = f2u(Bsc[(8 * kk + tq)     * BSTR + bc]);
                unsigned b1 = f2u(Bsc[(8 * kk + tq + 4) * BSTR + bc]);
                mma_tf32(acc[0][nt], a[0][0], a[0][1], a[0][2], a[0][3], b0, b1);
                mma_tf32(acc[1][nt], a[1][0], a[1][1], a[1][2], a[1][3], b0, b1);
            }
        }
        __syncthreads();
    }

    #pragma unroll
    for (int mt = 0; mt < 2; mt++) {
        #pragma unroll
        for (int rr = 0; rr < 2; rr++) {
            int row = m0 + 32 * wm + 16 * mt + g + 8 * rr;
            #pragma unroll
            for (int nt = 0; nt < NT; nt++) {
                int col = n0 + (BN / 2) * wn + 8 * nt + 2 * tq;
                float x0 = acc[mt][nt][2 * rr + 0];
                float x1 = acc[mt][nt][2 * rr + 1];
                if (STAGE == 1) {
                    x0 += bias[col];
                    x1 += bias[col + 1];
                    x0 = 0.5f * x0 * (1.0f + erff(x0 * 0.70710678118654752f));
                    x1 = 0.5f * x1 * (1.0f + erff(x1 * 0.70710678118654752f));
                    x0 += resid[(size_t)row * N + col];
                    x1 += resid[(size_t)row * N + col + 1];
                }
                *(float2*)&C[(size_t)row * N + col] = make_float2(x0, x1);
            }
        }
    }
}

// ---------------------------------------------------------------- tf32 flash attention + xyz agg
// 256 threads (8 warps), 128-query tile, 64-key tiles, 2-stage cp.async K/V,
// per-warp private P region, no-max exp2 softmax (log2e folded into Q scale).
#define KSTR 68
#define VSTR 72
#define PSTR 68
#define ATTN_SMEM ((2*64*KSTR + 2*64*VSTR + 128*PSTR) * 4)

__device__ __forceinline__ void attn_load_stage(const float* __restrict__ kbase,
                                                const float* __restrict__ vbase,
                                                const float* __restrict__ xyzb,
                                                int j0, float* kb, float* vb, int t) {
    #pragma unroll
    for (int u = 0; u < 4; u++) {
        int idx = t + 256 * u;
        int r = idx >> 4, c = (idx & 15) * 4;
        cp16(&kb[r * KSTR + c], kbase + (size_t)(j0 + r) * QKVD + c);
        cp16(&vb[r * VSTR + c], vbase + (size_t)(j0 + r) * QKVD + c);
    }
    if (t < 64) {
        const float* gx = xyzb + (size_t)(j0 + t) * 3;
        cp4(&vb[t * VSTR + 64], gx);
        cp4(&vb[t * VSTR + 65], gx + 1);
        cp4(&vb[t * VSTR + 66], gx + 2);
    }
}

__global__ __launch_bounds__(256, 2) void attn_kernel(const float* __restrict__ xyzs,
                                                      const float* __restrict__ w_sp) {
    extern __shared__ float sm[];
    float* kbuf0 = sm;
    float* kbuf1 = sm + 64 * KSTR;
    float* vbuf0 = sm + 2 * 64 * KSTR;
    float* vbuf1 = vbuf0 + 64 * VSTR;
    float* pb    = vbuf0 + 2 * 64 * VSTR;

    int bh = blockIdx.y;
    int b = bh >> 3, h = bh & 7;
    int i0 = blockIdx.x * 128;
    int t = threadIdx.x;
    int w = t >> 5, lane = t & 31;
    int g = lane >> 2, tq = lane & 3;

    const float* qkvb = g_qkv + (size_t)b * MM * QKVD;
    const float* xyzb = xyzs + (size_t)b * MM * 3;
    const float* kbase = qkvb + INNER + h * DHD;
    const float* vbase = qkvb + 2 * INNER + h * DHD;

    // zero pad cols 67..71 in both V buffers (written once)
    if (t < 128) {
        float* vv = ((t < 64) ? vbuf0 : vbuf1) + (t & 63) * VSTR;
        #pragma unroll
        for (int c = 67; c < 72; c++) vv[c] = 0.f;
    }

    attn_load_stage(kbase, vbase, xyzb, 0, kbuf0, vbuf0, t);
    CP_COMMIT();

    // preload Q fragments; fold in 0.125 * log2(e) so p = 2^s
    const float QS = 0.125f * 1.4426950408889634f;
    unsigned qf[8][4];
    {
        int r0 = i0 + 16 * w + g;
        const float* qp0 = qkvb + (size_t)r0 * QKVD + h * DHD;
        const float* qp1 = qp0 + 8 * QKVD;
        #pragma unroll
        for (int k0 = 0; k0 < 8; k0++) {
            qf[k0][0] = f2u(qp0[8 * k0 + tq]     * QS);
            qf[k0][1] = f2u(qp1[8 * k0 + tq]     * QS);
            qf[k0][2] = f2u(qp0[8 * k0 + tq + 4] * QS);
            qf[k0][3] = f2u(qp1[8 * k0 + tq + 4] * QS);
        }
    }

    float of[9][4] = {};
    float l0 = 0.f, l1 = 0.f;
    int pr0 = 16 * w + g, pr1 = pr0 + 8;

    for (int jt = 0; jt < 32; jt++) {
        float* kb = (jt & 1) ? kbuf1 : kbuf0;
        float* vb = (jt & 1) ? vbuf1 : vbuf0;
        if (jt < 31) {
            float* kn = (jt & 1) ? kbuf0 : kbuf1;
            float* vn = (jt & 1) ? vbuf0 : vbuf1;
            attn_load_stage(kbase, vbase, xyzb, (jt + 1) * 64, kn, vn, t);
            CP_COMMIT();
            CP_WAIT(1);
        } else {
            CP_WAIT(0);
        }
        __syncthreads();

        // S = Q K^T -> p = 2^s inline per n-tile -> P store (warp-private rows)
        #pragma unroll
        for (int n = 0; n < 8; n++) {
            float s[4] = {};
            const float* kbp = &kb[(8 * n + g) * KSTR];
            #pragma unroll
            for (int k0 = 0; k0 < 8; k0++) {
                unsigned b0 = f2u(kbp[8 * k0 + tq]);
                unsigned b1 = f2u(kbp[8 * k0 + tq + 4]);
                mma_tf32(s, qf[k0][0], qf[k0][1], qf[k0][2], qf[k0][3], b0, b1);
            }
            s[0] = ex2(s[0]); s[1] = ex2(s[1]);
            s[2] = ex2(s[2]); s[3] = ex2(s[3]);
            l0 += s[0] + s[1];
            l1 += s[2] + s[3];
            int col = 8 * n + 2 * tq;
            *(float2*)&pb[pr0 * PSTR + col] = make_float2(s[0], s[1]);
            *(float2*)&pb[pr1 * PSTR + col] = make_float2(s[2], s[3]);
        }
        __syncwarp();

        // O += P V_ext (cols 64..66 carry attn@xyz)
        #pragma unroll
        for (int k0 = 0; k0 < 8; k0++) {
            unsigned a0 = f2u(pb[pr0 * PSTR + 8 * k0 + tq]);
            unsigned a1 = f2u(pb[pr1 * PSTR + 8 * k0 + tq]);
            unsigned a2 = f2u(pb[pr0 * PSTR + 8 * k0 + tq + 4]);
            unsigned a3 = f2u(pb[pr1 * PSTR + 8 * k0 + tq + 4]);
            const float* vb0 = &vb[(8 * k0 + tq)     * VSTR + g];
            const float* vb1 = &vb[(8 * k0 + tq + 4) * VSTR + g];
            #pragma unroll
            for (int n = 0; n < 9; n++) {
                unsigned b0 = f2u(vb0[8 * n]);
                unsigned b1 = f2u(vb1[8 * n]);
                mma_tf32(of[n], a0, a1, a2, a3, b0, b1);
            }
        }
        __syncthreads();
    }

    // row-sum reduce across quad (once, post-loop)
    #pragma unroll
    for (int o = 1; o < 4; o <<= 1) {
        l0 += __shfl_xor_sync(0xffffffffu, l0, o);
        l1 += __shfl_xor_sync(0xffffffffu, l1, o);
    }

    // epilogue
    float invl0 = 1.0f / l0, invl1 = 1.0f / l1;
    int base = lane & ~3;
    float ax0_0 = __shfl_sync(0xffffffffu, of[8][0], base + 0);
    float ax1_0 = __shfl_sync(0xffffffffu, of[8][1], base + 0);
    float ax2_0 = __shfl_sync(0xffffffffu, of[8][0], base + 1);
    float ax0_1 = __shfl_sync(0xffffffffu, of[8][2], base + 0);
    float ax1_1 = __shfl_sync(0xffffffffu, of[8][3], base + 0);
    float ax2_1 = __shfl_sync(0xffffffffu, of[8][2], base + 1);

    int row0 = i0 + 16 * w + g, row1 = row0 + 8;
    const float* xq0 = xyzs + ((size_t)b * MM + row0) * 3;
    const float* xq1 = xyzs + ((size_t)b * MM + row1) * 3;
    float a00 = ax0_0 * invl0 - xq0[0];
    float a10 = ax1_0 * invl0 - xq0[1];
    float a20 = ax2_0 * invl0 - xq0[2];
    float a01 = ax0_1 * invl1 - xq1[0];
    float a11 = ax1_1 * invl1 - xq1[1];
    float a21 = ax2_1 * invl1 - xq1[2];

    float* orow0 = g_outpre + ((size_t)b * MM + row0) * INNER + h * DHD;
    float* orow1 = g_outpre + ((size_t)b * MM + row1) * INNER + h * DHD;
    #pragma unroll
    for (int n = 0; n < 8; n++) {
        int d = 8 * n + 2 * tq;
        float w00 = w_sp[d],       w01 = w_sp[d + 1];
        float w10 = w_sp[64 + d],  w11 = w_sp[64 + d + 1];
        float w20 = w_sp[128 + d], w21 = w_sp[128 + d + 1];
        float o00 = of[n][0] * invl0 + a00 * w00 + a10 * w10 + a20 * w20;
        float o01 = of[n][1] * invl0 + a00 * w01 + a10 * w11 + a20 * w21;
        float o10 = of[n][2] * invl1 + a01 * w00 + a11 * w10 + a21 * w20;
        float o11 = of[n][3] * invl1 + a01 * w01 + a11 * w11 + a21 * w21;
        *(float2*)&orow0[d] = make_float2(o00, o01);
        *(float2*)&orow1[d] = make_float2(o10, o11);
    }
}

// ---------------------------------------------------------------- launch
extern "C" void kernel_launch(void* const* d_in, const int* in_sizes, int n_in,
                              void* d_out, int out_size) {
    const float* xyzs     = (const float*)d_in[0];
    const float* features = (const float*)d_in[1];
    const float* gamma    = (const float*)d_in[2];
    const float* beta     = (const float*)d_in[3];
    const float* w_qkv    = (const float*)d_in[4];
    const float* w_sp     = (const float*)d_in[5];
    const float* w_out    = (const float*)d_in[6];
    const float* b_out    = (const float*)d_in[7];
    float* out = (float*)d_out;

    const int g0_smem = 2 * (128 * 36 + 32 * 136) * 4;   // 71680
    const int g1_smem = 2 * (128 * 36 + 32 * 72) * 4;    // 55296
    cudaFuncSetAttribute(gemm_tf32<0, 128>, cudaFuncAttributeMaxDynamicSharedMemorySize, g0_smem);
    cudaFuncSetAttribute(gemm_tf32<1, 64>,  cudaFuncAttributeMaxDynamicSharedMemorySize, g1_smem);
    cudaFuncSetAttribute(attn_kernel, cudaFuncAttributeMaxDynamicSharedMemorySize, ATTN_SMEM);

    ln_kernel<<<ROWS, 256>>>(features, gamma, beta);
    gemm_tf32<0, 128><<<dim3(QKVD / 128, ROWS / 128), 256, g0_smem>>>(w_qkv, nullptr, nullptr, nullptr, QKVD);
    attn_kernel<<<dim3(MM / 128, BB * HEADS), 256, ATTN_SMEM>>>(xyzs, w_sp);
    gemm_tf32<1, 64><<<dim3(DIMF / 64, ROWS / 128), 256, g1_smem>>>(w_out, b_out, features, out, DIMF);
}

// round 12
// speedup vs baseline: 2.1723x; 1.5612x over previous
#include <cuda_runtime.h>
#include <cuda_bf16.h>
#include <math.h>

#define BB    2
#define MM    2048
#define DIMF  512
#define HEADS 8
#define DHD   64
#define INNER 512
#define QKVD  1536
#define ROWS  (BB*MM)       // 4096

__device__ float g_normed[ROWS * DIMF];
__device__ float g_outpre[ROWS * INNER];
__device__ __nv_bfloat16 g_qk[ROWS * 1024];        // cols 0..511 Q (pre-scaled), 512..1023 K
__device__ __nv_bfloat16 g_vT[BB * INNER * MM];    // [b][d][token]
__device__ __nv_bfloat16 g_xyzT[BB * 3 * MM];      // [b][c][token]

__device__ __forceinline__ void mma_tf32(float c[4],
                                         unsigned a0, unsigned a1, unsigned a2, unsigned a3,
                                         unsigned b0, unsigned b1) {
    asm volatile(
        "mma.sync.aligned.m16n8k8.row.col.f32.tf32.tf32.f32 "
        "{%0,%1,%2,%3}, {%4,%5,%6,%7}, {%8,%9}, {%0,%1,%2,%3};\n"
        : "+f"(c[0]), "+f"(c[1]), "+f"(c[2]), "+f"(c[3])
        : "r"(a0), "r"(a1), "r"(a2), "r"(a3), "r"(b0), "r"(b1));
}
__device__ __forceinline__ void mma_bf16(float c[4],
                                         unsigned a0, unsigned a1, unsigned a2, unsigned a3,
                                         unsigned b0, unsigned b1) {
    asm volatile(
        "mma.sync.aligned.m16n8k16.row.col.f32.bf16.bf16.f32 "
        "{%0,%1,%2,%3}, {%4,%5,%6,%7}, {%8,%9}, {%0,%1,%2,%3};\n"
        : "+f"(c[0]), "+f"(c[1]), "+f"(c[2]), "+f"(c[3])
        : "r"(a0), "r"(a1), "r"(a2), "r"(a3), "r"(b0), "r"(b1));
}
__device__ __forceinline__ void ldsm4(unsigned r[4], unsigned addr) {
    asm volatile("ldmatrix.sync.aligned.m8n8.x4.shared.b16 {%0,%1,%2,%3}, [%4];"
                 : "=r"(r[0]), "=r"(r[1]), "=r"(r[2]), "=r"(r[3]) : "r"(addr));
}
__device__ __forceinline__ unsigned f2u(float x) { return __float_as_uint(x); }
__device__ __forceinline__ unsigned pack_bf16(float lo, float hi) {
    unsigned r; asm("cvt.rn.bf16x2.f32 %0, %1, %2;" : "=r"(r) : "f"(hi), "f"(lo)); return r;
}
__device__ __forceinline__ float ex2(float x) {
    float y; asm("ex2.approx.ftz.f32 %0, %1;" : "=f"(y) : "f"(x)); return y;
}
__device__ __forceinline__ void cp16(void* s, const void* g) {
    unsigned sa = (unsigned)__cvta_generic_to_shared(s);
    asm volatile("cp.async.ca.shared.global [%0], [%1], 16;\n" :: "r"(sa), "l"(g));
}
#define CP_COMMIT() asm volatile("cp.async.commit_group;\n" ::: "memory")
#define CP_WAIT(n)  asm volatile("cp.async.wait_group %0;\n" :: "n"(n) : "memory")

// ---------------------------------------------------------------- LayerNorm
__global__ void ln_kernel(const float* __restrict__ x,
                          const float* __restrict__ gamma,
                          const float* __restrict__ beta) {
    int row = blockIdx.x;
    int t = threadIdx.x;
    const float* xr = x + (size_t)row * DIMF;
    float v0 = xr[t], v1 = xr[t + 256];
    float s = v0 + v1, ss = v0 * v0 + v1 * v1;
    #pragma unroll
    for (int o = 16; o > 0; o >>= 1) {
        s  += __shfl_xor_sync(0xffffffffu, s, o);
        ss += __shfl_xor_sync(0xffffffffu, ss, o);
    }
    __shared__ float ws[8], wss[8];
    if ((t & 31) == 0) { ws[t >> 5] = s; wss[t >> 5] = ss; }
    __syncthreads();
    float S = 0.f, SS = 0.f;
    #pragma unroll
    for (int i = 0; i < 8; i++) { S += ws[i]; SS += wss[i]; }
    float mean = S * (1.0f / DIMF);
    float var  = SS * (1.0f / DIMF) - mean * mean;
    float inv  = rsqrtf(var + 1e-5f);
    float* o = g_normed + (size_t)row * DIMF;
    o[t]       = (v0 - mean) * inv * gamma[t]       + beta[t];
    o[t + 256] = (v1 - mean) * inv * gamma[t + 256] + beta[t + 256];
}

// ---------------------------------------------------------------- xyz transpose to bf16
__global__ void xyzT_kernel(const float* __restrict__ xyzs) {
    int i = blockIdx.x * 256 + threadIdx.x;
    if (i < BB * 3 * MM) {
        int b = i / (3 * MM), r = i % (3 * MM);
        int c = r / MM, m = r % MM;
        g_xyzT[i] = __float2bfloat16(xyzs[((size_t)b * MM + m) * 3 + c]);
    }
}

// ---------------------------------------------------------------- tf32 GEMM, 2-stage cp.async
// STAGE0: g_normed @ w_qkv -> bf16 Q(scaled)/K into g_qk, V transposed into g_vT
// STAGE1: g_outpre @ w_out + bias, GELU, + residual -> out (fp32)
template <int BN>
__device__ __forceinline__ void gemm_load(const float* __restrict__ A,
                                          const float* __restrict__ Bmat,
                                          float* Asd, float* Bsd,
                                          int m0, int n0, int N, int k0, int t) {
    constexpr int BSTR = BN + 8;
    #pragma unroll
    for (int i = 0; i < 4; i++) {
        int lin = t + i * 256;
        int r = lin >> 3, c = (lin & 7) * 4;
        cp16(&Asd[r * 36 + c], &A[(size_t)(m0 + r) * 512 + k0 + c]);
    }
    #pragma unroll
    for (int i = 0; i < BN / 32; i++) {
        int lin = t + i * 256;
        int r = lin / (BN / 4), c = (lin % (BN / 4)) * 4;
        cp16(&Bsd[r * BSTR + c], &Bmat[(size_t)(k0 + r) * N + n0 + c]);
    }
}

template <int STAGE, int BN>
__global__ __launch_bounds__(256, 2) void gemm_tf32(const float* __restrict__ Bmat,
                          const float* __restrict__ bias,
                          const float* __restrict__ resid,
                          float* __restrict__ CoutP, int N) {
    constexpr int BSTR = BN + 8;
    constexpr int NT = BN / 16;
    const float* A = (STAGE == 0) ? g_normed : g_outpre;
    extern __shared__ float smem[];
    float* As0 = smem;
    float* As1 = smem + 128 * 36;
    float* Bs0 = smem + 2 * 128 * 36;
    float* Bs1 = Bs0 + 32 * BSTR;

    int m0 = blockIdx.y * 128, n0 = blockIdx.x * BN;
    int t = threadIdx.x;
    int w = t >> 5, lane = t & 31;
    int wm = w >> 1, wn = w & 1;
    int g = lane >> 2, tq = lane & 3;

    float acc[2][NT][4] = {};

    gemm_load<BN>(A, Bmat, As0, Bs0, m0, n0, N, 0, t);
    CP_COMMIT();

    for (int kc = 0; kc < 16; kc++) {
        float* Asc = (kc & 1) ? As1 : As0;
        float* Bsc = (kc & 1) ? Bs1 : Bs0;
        if (kc < 15) {
            float* Asn = (kc & 1) ? As0 : As1;
            float* Bsn = (kc & 1) ? Bs0 : Bs1;
            gemm_load<BN>(A, Bmat, Asn, Bsn, m0, n0, N, (kc + 1) * 32, t);
            CP_COMMIT();
            CP_WAIT(1);
        } else {
            CP_WAIT(0);
        }
        __syncthreads();
        #pragma unroll
        for (int kk = 0; kk < 4; kk++) {
            unsigned a[2][4];
            #pragma unroll
            for (int mt = 0; mt < 2; mt++) {
                int br = 32 * wm + 16 * mt;
                a[mt][0] = f2u(Asc[(br + g)     * 36 + 8 * kk + tq]);
                a[mt][1] = f2u(Asc[(br + 8 + g) * 36 + 8 * kk + tq]);
                a[mt][2] = f2u(Asc[(br + g)     * 36 + 8 * kk + tq + 4]);
                a[mt][3] = f2u(Asc[(br + 8 + g) * 36 + 8 * kk + tq + 4]);
            }
            #pragma unroll
            for (int nt = 0; nt < NT; nt++) {
                int bc = (BN / 2) * wn + 8 * nt + g;
                unsigned b0 = f2u(Bsc[(8 * kk + tq)     * BSTR + bc]);
                unsigned b1 = f2u(Bsc[(8 * kk + tq + 4) * BSTR + bc]);
                mma_tf32(acc[0][nt], a[0][0], a[0][1], a[0][2], a[0][3], b0, b1);
                mma_tf32(acc[1][nt], a[1][0], a[1][1], a[1][2], a[1][3], b0, b1);
            }
        }
        __syncthreads();
    }

    const float QS = 0.125f * 1.4426950408889634f;   // softmax scale * log2(e)
    #pragma unroll
    for (int mt = 0; mt < 2; mt++) {
        #pragma unroll
        for (int rr = 0; rr < 2; rr++) {
            int row = m0 + 32 * wm + 16 * mt + g + 8 * rr;
            #pragma unroll
            for (int nt = 0; nt < NT; nt++) {
                int col = n0 + (BN / 2) * wn + 8 * nt + 2 * tq;
                float x0 = acc[mt][nt][2 * rr + 0];
                float x1 = acc[mt][nt][2 * rr + 1];
                if (STAGE == 0) {
                    if (n0 < 512) {           // Q: fold softmax scale, bf16
                        __nv_bfloat162 p;
                        p.x = __float2bfloat16(x0 * QS);
                        p.y = __float2bfloat16(x1 * QS);
                        *(__nv_bfloat162*)&g_qk[(size_t)row * 1024 + col] = p;
                    } else if (n0 < 1024) {   // K: bf16 row-major
                        __nv_bfloat162 p;
                        p.x = __float2bfloat16(x0);
                        p.y = __float2bfloat16(x1);
                        *(__nv_bfloat162*)&g_qk[(size_t)row * 1024 + col] = p;
                    } else {                  // V: bf16 transposed [b][d][token]
                        int d = col - 1024, bb = row >> 11, tok = row & 2047;
                        g_vT[((size_t)bb * INNER + d)     * MM + tok] = __float2bfloat16(x0);
                        g_vT[((size_t)bb * INNER + d + 1) * MM + tok] = __float2bfloat16(x1);
                    }
                } else {
                    x0 += bias[col];
                    x1 += bias[col + 1];
                    x0 = 0.5f * x0 * (1.0f + erff(x0 * 0.70710678118654752f));
                    x1 = 0.5f * x1 * (1.0f + erff(x1 * 0.70710678118654752f));
                    x0 += resid[(size_t)row * N + col];
                    x1 += resid[(size_t)row * N + col + 1];
                    *(float2*)&CoutP[(size_t)row * N + col] = make_float2(x0, x1);
                }
            }
        }
    }
}

// ---------------------------------------------------------------- bf16 flash attention + xyz agg
// 256 threads (8 warps), 128-query tile, 64-key tiles, 2-stage cp.async,
// m16n8k16 bf16 MMA, ldmatrix B-frags, register P (fp32 C-layout -> bf16 A-layout).
#define KST 72   // bf16 elems per K smem row (144B, 16B-aligned)
#define VST 72
#define ATTN_SMEM ((2*64*KST + 2*72*VST) * 2)

__device__ __forceinline__ void attn_load_stage(const __nv_bfloat16* __restrict__ kg,
                                                const __nv_bfloat16* __restrict__ vg,
                                                const __nv_bfloat16* __restrict__ xg,
                                                int j0, __nv_bfloat16* kb, __nv_bfloat16* vb, int t) {
    #pragma unroll
    for (int u = 0; u < 2; u++) {
        int idx = t + 256 * u;
        int r = idx >> 3, seg = (idx & 7) * 8;
        cp16(&kb[r * KST + seg], kg + (size_t)(j0 + r) * 1024 + seg);
        cp16(&vb[r * VST + seg], vg + (size_t)r * MM + j0 + seg);
    }
    if (t < 24) {
        int c = t >> 3, seg = (t & 7) * 8;
        cp16(&vb[(64 + c) * VST + seg], xg + (size_t)c * MM + j0 + seg);
    }
}

__global__ __launch_bounds__(256, 2) void attn_kernel(const float* __restrict__ xyzs,
                                                      const float* __restrict__ w_sp) {
    extern __shared__ __nv_bfloat16 smb[];
    __nv_bfloat16* kbuf0 = smb;
    __nv_bfloat16* kbuf1 = smb + 64 * KST;
    __nv_bfloat16* vbuf0 = smb + 2 * 64 * KST;
    __nv_bfloat16* vbuf1 = vbuf0 + 72 * VST;

    int bh = blockIdx.y;
    int b = bh >> 3, h = bh & 7;
    int i0 = blockIdx.x * 128;
    int t = threadIdx.x;
    int w = t >> 5, lane = t & 31;
    int g = lane >> 2, tq = lane & 3;

    const __nv_bfloat16* kg = g_qk + 512 + h * DHD;                       // K cols
    const __nv_bfloat16* vg = g_vT + ((size_t)b * INNER + h * DHD) * MM;  // V^T rows
    const __nv_bfloat16* xg = g_xyzT + (size_t)b * 3 * MM;
    const __nv_bfloat16* kgb = kg + (size_t)0;   // row-indexed with batch offset below

    // zero V^T pad rows 67..71 (cols 0..63) in both buffers, written once
    for (int i = t; i < 2 * 5 * 64; i += 256) {
        int buf = i / (5 * 64), rr = (i / 64) % 5, cc = i & 63;
        (buf ? vbuf1 : vbuf0)[(67 + rr) * VST + cc] = __float2bfloat16(0.f);
    }

    const __nv_bfloat16* kgbase = kg + (size_t)b * MM * 1024;
    attn_load_stage(kgbase, vg, xg, 0, kbuf0, vbuf0, t);
    CP_COMMIT();

    // Q fragments (bf16, pre-scaled in gemm0): 4 k-chunks of 16
    unsigned qf[4][4];
    {
        const __nv_bfloat16* q0 = g_qk + (size_t)(b * MM + i0 + 16 * w + g) * 1024 + h * DHD;
        const __nv_bfloat16* q1 = q0 + 8 * 1024;
        #pragma unroll
        for (int kc = 0; kc < 4; kc++) {
            qf[kc][0] = *(const unsigned*)(q0 + 16 * kc + 2 * tq);
            qf[kc][1] = *(const unsigned*)(q1 + 16 * kc + 2 * tq);
            qf[kc][2] = *(const unsigned*)(q0 + 16 * kc + 8 + 2 * tq);
            qf[kc][3] = *(const unsigned*)(q1 + 16 * kc + 8 + 2 * tq);
        }
    }

    float of[9][4] = {};
    float l0 = 0.f, l1 = 0.f;
    unsigned lmbase = (lane & 7) * (KST * 2) + (lane >> 3) * 16;   // byte offset within tile

    for (int jt = 0; jt < 32; jt++) {
        __nv_bfloat16* kb = (jt & 1) ? kbuf1 : kbuf0;
        __nv_bfloat16* vb = (jt & 1) ? vbuf1 : vbuf0;
        if (jt < 31) {
            __nv_bfloat16* kn = (jt & 1) ? kbuf0 : kbuf1;
            __nv_bfloat16* vn = (jt & 1) ? vbuf0 : vbuf1;
            attn_load_stage(kgbase, vg, xg, (jt + 1) * 64, kn, vn, t);
            CP_COMMIT();
            CP_WAIT(1);
        } else {
            CP_WAIT(0);
        }
        __syncthreads();

        // S = Q K^T  (8 n-tiles of 16x8; 4 bf16 mma each)
        float sacc[8][4] = {};
        unsigned kaddr = (unsigned)__cvta_generic_to_shared(kb) + lmbase;
        #pragma unroll
        for (int n = 0; n < 8; n++) {
            unsigned b8[8];
            ldsm4(b8,     kaddr);
            ldsm4(b8 + 4, kaddr + 64);
            kaddr += 8 * KST * 2;
            #pragma unroll
            for (int kc = 0; kc < 4; kc++)
                mma_bf16(sacc[n], qf[kc][0], qf[kc][1], qf[kc][2], qf[kc][3],
                         b8[2 * kc], b8[2 * kc + 1]);
        }

        // p = 2^s (no-max softmax), accumulate row sums
        #pragma unroll
        for (int n = 0; n < 8; n++) {
            sacc[n][0] = ex2(sacc[n][0]); sacc[n][1] = ex2(sacc[n][1]);
            sacc[n][2] = ex2(sacc[n][2]); sacc[n][3] = ex2(sacc[n][3]);
            l0 += sacc[n][0] + sacc[n][1];
            l1 += sacc[n][2] + sacc[n][3];
        }

        // pack P into bf16 A-fragments (C-layout pairs == A-layout pairs)
        unsigned pf[4][4];
        #pragma unroll
        for (int kc = 0; kc < 4; kc++) {
            pf[kc][0] = pack_bf16(sacc[2 * kc][0],     sacc[2 * kc][1]);
            pf[kc][1] = pack_bf16(sacc[2 * kc][2],     sacc[2 * kc][3]);
            pf[kc][2] = pack_bf16(sacc[2 * kc + 1][0], sacc[2 * kc + 1][1]);
            pf[kc][3] = pack_bf16(sacc[2 * kc + 1][2], sacc[2 * kc + 1][3]);
        }

        // O += P V_ext (V^T rows 64..66 = xyz -> attn@xyz for free)
        unsigned vaddr = (unsigned)__cvta_generic_to_shared(vb) + lmbase;
        #pragma unroll
        for (int nt = 0; nt < 9; nt++) {
            unsigned v8[8];
            ldsm4(v8,     vaddr);
            ldsm4(v8 + 4, vaddr + 64);
            vaddr += 8 * VST * 2;
            #pragma unroll
            for (int kc = 0; kc < 4; kc++)
                mma_bf16(of[nt], pf[kc][0], pf[kc][1], pf[kc][2], pf[kc][3],
                         v8[2 * kc], v8[2 * kc + 1]);
        }
        __syncthreads();
    }

    // row-sum reduce across quad
    #pragma unroll
    for (int o = 1; o < 4; o <<= 1) {
        l0 += __shfl_xor_sync(0xffffffffu, l0, o);
        l1 += __shfl_xor_sync(0xffffffffu, l1, o);
    }

    // epilogue (of[8]: cols 64..66 = attn@xyz)
    float invl0 = 1.0f / l0, invl1 = 1.0f / l1;
    int base = lane & ~3;
    float ax0_0 = __shfl_sync(0xffffffffu, of[8][0], base + 0);
    float ax1_0 = __shfl_sync(0xffffffffu, of[8][1], base + 0);
    float ax2_0 = __shfl_sync(0xffffffffu, of[8][0], base + 1);
    float ax0_1 = __shfl_sync(0xffffffffu, of[8][2], base + 0);
    float ax1_1 = __shfl_sync(0xffffffffu, of[8][3], base + 0);
    float ax2_1 = __shfl_sync(0xffffffffu, of[8][2], base + 1);

    int row0 = i0 + 16 * w + g, row1 = row0 + 8;
    const float* xq0 = xyzs + ((size_t)b * MM + row0) * 3;
    const float* xq1 = xyzs + ((size_t)b * MM + row1) * 3;
    float a00 = ax0_0 * invl0 - xq0[0];
    float a10 = ax1_0 * invl0 - xq0[1];
    float a20 = ax2_0 * invl0 - xq0[2];
    float a01 = ax0_1 * invl1 - xq1[0];
    float a11 = ax1_1 * invl1 - xq1[1];
    float a21 = ax2_1 * invl1 - xq1[2];

    float* orow0 = g_outpre + ((size_t)b * MM + row0) * INNER + h * DHD;
    float* orow1 = g_outpre + ((size_t)b * MM + row1) * INNER + h * DHD;
    #pragma unroll
    for (int n = 0; n < 8; n++) {
        int d = 8 * n + 2 * tq;
        float w00 = w_sp[d],       w01 = w_sp[d + 1];
        float w10 = w_sp[64 + d],  w11 = w_sp[64 + d + 1];
        float w20 = w_sp[128 + d], w21 = w_sp[128 + d + 1];
        float o00 = of[n][0] * invl0 + a00 * w00 + a10 * w10 + a20 * w20;
        float o01 = of[n][1] * invl0 + a00 * w01 + a10 * w11 + a20 * w21;
        float o10 = of[n][2] * invl1 + a01 * w00 + a11 * w10 + a21 * w20;
        float o11 = of[n][3] * invl1 + a01 * w01 + a11 * w11 + a21 * w21;
        *(float2*)&orow0[d] = make_float2(o00, o01);
        *(float2*)&orow1[d] = make_float2(o10, o11);
    }
}

// ---------------------------------------------------------------- launch
extern "C" void kernel_launch(void* const* d_in, const int* in_sizes, int n_in,
                              void* d_out, int out_size) {
    const float* xyzs     = (const float*)d_in[0];
    const float* features = (const float*)d_in[1];
    const float* gamma    = (const float*)d_in[2];
    const float* beta     = (const float*)d_in[3];
    const float* w_qkv    = (const float*)d_in[4];
    const float* w_sp     = (const float*)d_in[5];
    const float* w_out    = (const float*)d_in[6];
    const float* b_out    = (const float*)d_in[7];
    float* out = (float*)d_out;

    const int g0_smem = 2 * (128 * 36 + 32 * 136) * 4;   // 71680
    const int g1_smem = 2 * (128 * 36 + 32 * 72) * 4;    // 55296
    cudaFuncSetAttribute(gemm_tf32<0, 128>, cudaFuncAttributeMaxDynamicSharedMemorySize, g0_smem);
    cudaFuncSetAttribute(gemm_tf32<1, 64>,  cudaFuncAttributeMaxDynamicSharedMemorySize, g1_smem);
    cudaFuncSetAttribute(attn_kernel, cudaFuncAttributeMaxDynamicSharedMemorySize, ATTN_SMEM);

    ln_kernel<<<ROWS, 256>>>(features, gamma, beta);
    xyzT_kernel<<<(BB * 3 * MM + 255) / 256, 256>>>(xyzs);
    gemm_tf32<0, 128><<<dim3(QKVD / 128, ROWS / 128), 256, g0_smem>>>(w_qkv, nullptr, nullptr, nullptr, QKVD);
    attn_kernel<<<dim3(MM / 128, BB * HEADS), 256, ATTN_SMEM>>>(xyzs, w_sp);
    gemm_tf32<1, 64><<<dim3(DIMF / 64, ROWS / 128), 256, g1_smem>>>(w_out, b_out, features, out, DIMF);
}

// round 13
// speedup vs baseline: 2.7782x; 1.2789x over previous
#include <cuda_runtime.h>
#include <cuda_bf16.h>
#include <math.h>

#define BB    2
#define MM    2048
#define DIMF  512
#define HEADS 8
#define DHD   64
#define INNER 512
#define QKVD  1536
#define ROWS  (BB*MM)       // 4096

__device__ __nv_bfloat16 g_normed[ROWS * DIMF];    // LN output, bf16
__device__ __nv_bfloat16 g_outpre[ROWS * INNER];   // attention output, bf16
__device__ __nv_bfloat16 g_wqkv[DIMF * QKVD];
__device__ __nv_bfloat16 g_wout[DIMF * DIMF];
__device__ __nv_bfloat16 g_qk[ROWS * 1024];        // cols 0..511 Q (pre-scaled), 512..1023 K
__device__ __nv_bfloat16 g_vT[BB * INNER * MM];    // [b][d][token]
__device__ __nv_bfloat16 g_xyzT[BB * 3 * MM];      // [b][c][token]

__device__ __forceinline__ void mma_bf16(float c[4],
                                         unsigned a0, unsigned a1, unsigned a2, unsigned a3,
                                         unsigned b0, unsigned b1) {
    asm volatile(
        "mma.sync.aligned.m16n8k16.row.col.f32.bf16.bf16.f32 "
        "{%0,%1,%2,%3}, {%4,%5,%6,%7}, {%8,%9}, {%0,%1,%2,%3};\n"
        : "+f"(c[0]), "+f"(c[1]), "+f"(c[2]), "+f"(c[3])
        : "r"(a0), "r"(a1), "r"(a2), "r"(a3), "r"(b0), "r"(b1));
}
__device__ __forceinline__ void ldsm4(unsigned r[4], unsigned addr) {
    asm volatile("ldmatrix.sync.aligned.m8n8.x4.shared.b16 {%0,%1,%2,%3}, [%4];"
                 : "=r"(r[0]), "=r"(r[1]), "=r"(r[2]), "=r"(r[3]) : "r"(addr));
}
__device__ __forceinline__ void ldsm4t(unsigned r[4], unsigned addr) {
    asm volatile("ldmatrix.sync.aligned.m8n8.x4.trans.shared.b16 {%0,%1,%2,%3}, [%4];"
                 : "=r"(r[0]), "=r"(r[1]), "=r"(r[2]), "=r"(r[3]) : "r"(addr));
}
__device__ __forceinline__ unsigned pack_bf16(float lo, float hi) {
    unsigned r; asm("cvt.rn.bf16x2.f32 %0, %1, %2;" : "=r"(r) : "f"(hi), "f"(lo)); return r;
}
__device__ __forceinline__ float ex2(float x) {
    float y; asm("ex2.approx.ftz.f32 %0, %1;" : "=f"(y) : "f"(x)); return y;
}
__device__ __forceinline__ void cp16(void* s, const void* g) {
    unsigned sa = (unsigned)__cvta_generic_to_shared(s);
    asm volatile("cp.async.ca.shared.global [%0], [%1], 16;\n" :: "r"(sa), "l"(g));
}
#define CP_COMMIT() asm volatile("cp.async.commit_group;\n" ::: "memory")
#define CP_WAIT(n)  asm volatile("cp.async.wait_group %0;\n" :: "n"(n) : "memory")

// ---------------------------------------------------------------- LayerNorm -> bf16
__global__ void ln_kernel(const float* __restrict__ x,
                          const float* __restrict__ gamma,
                          const float* __restrict__ beta) {
    int row = blockIdx.x;
    int t = threadIdx.x;
    const float* xr = x + (size_t)row * DIMF;
    float2 v = *(const float2*)&xr[2 * t];
    float s = v.x + v.y, ss = v.x * v.x + v.y * v.y;
    #pragma unroll
    for (int o = 16; o > 0; o >>= 1) {
        s  += __shfl_xor_sync(0xffffffffu, s, o);
        ss += __shfl_xor_sync(0xffffffffu, ss, o);
    }
    __shared__ float ws[8], wss[8];
    if ((t & 31) == 0) { ws[t >> 5] = s; wss[t >> 5] = ss; }
    __syncthreads();
    float S = 0.f, SS = 0.f;
    #pragma unroll
    for (int i = 0; i < 8; i++) { S += ws[i]; SS += wss[i]; }
    float mean = S * (1.0f / DIMF);
    float var  = SS * (1.0f / DIMF) - mean * mean;
    float inv  = rsqrtf(var + 1e-5f);
    float2 gm = *(const float2*)&gamma[2 * t];
    float2 bt = *(const float2*)&beta[2 * t];
    float n0 = (v.x - mean) * inv * gm.x + bt.x;
    float n1 = (v.y - mean) * inv * gm.y + bt.y;
    *(unsigned*)&g_normed[(size_t)row * DIMF + 2 * t] = pack_bf16(n0, n1);
}

// ---------------------------------------------------------------- weight + xyz conversion
__global__ void cvt_kernel(const float* __restrict__ wqkv,
                           const float* __restrict__ wout,
                           const float* __restrict__ xyzs) {
    int i = blockIdx.x * 256 + threadIdx.x;
    if (i < DIMF * QKVD) g_wqkv[i] = __float2bfloat16(wqkv[i]);
    if (i < DIMF * DIMF) g_wout[i] = __float2bfloat16(wout[i]);
    if (i < BB * 3 * MM) {
        int b = i / (3 * MM), r = i % (3 * MM);
        int c = r / MM, m = r % MM;
        g_xyzT[i] = __float2bfloat16(xyzs[((size_t)b * MM + m) * 3 + c]);
    }
}

// ---------------------------------------------------------------- bf16 GEMM0: 128x128, k-chunk 64
// g_normed @ g_wqkv -> bf16 Q(scaled)/K into g_qk, V transposed into g_vT
#define G0_ASTR 72
#define G0_BSTR 136
__device__ __forceinline__ void g0_load(const __nv_bfloat16* __restrict__ A,
                                        const __nv_bfloat16* __restrict__ B,
                                        __nv_bfloat16* Asd, __nv_bfloat16* Bsd,
                                        int m0, int n0, int k0, int t) {
    #pragma unroll
    for (int i = 0; i < 4; i++) {           // A: 128 rows x 64 cols
        int lin = t + i * 256;
        int r = lin >> 3, seg = (lin & 7) * 8;
        cp16(&Asd[r * G0_ASTR + seg], &A[(size_t)(m0 + r) * DIMF + k0 + seg]);
    }
    #pragma unroll
    for (int i = 0; i < 4; i++) {           // B: 64 rows x 128 cols
        int lin = t + i * 256;
        int r = lin >> 4, seg = (lin & 15) * 8;
        cp16(&Bsd[r * G0_BSTR + seg], &B[(size_t)(k0 + r) * QKVD + n0 + seg]);
    }
}

__global__ __launch_bounds__(256, 2) void gemm0_bf16() {
    extern __shared__ __nv_bfloat16 smb[];
    __nv_bfloat16* As0 = smb;
    __nv_bfloat16* As1 = As0 + 128 * G0_ASTR;
    __nv_bfloat16* Bs0 = As1 + 128 * G0_ASTR;
    __nv_bfloat16* Bs1 = Bs0 + 64 * G0_BSTR;

    int m0 = blockIdx.y * 128, n0 = blockIdx.x * 128;
    int t = threadIdx.x;
    int w = t >> 5, lane = t & 31;
    int wm = w >> 1, wn = w & 1;            // warp tile 32x64
    int g = lane >> 2, tq = lane & 3;
    unsigned lm = (lane & 15) * (G0_ASTR * 2) + (lane >> 4) * 16;   // A byte offset
    unsigned lmB = (lane & 15) * (G0_BSTR * 2) + (lane >> 4) * 16;  // B byte offset

    float acc[2][8][4] = {};

    g0_load(g_normed, g_wqkv, As0, Bs0, m0, n0, 0, t);
    CP_COMMIT();

    for (int kc8 = 0; kc8 < 8; kc8++) {
        __nv_bfloat16* Asc = (kc8 & 1) ? As1 : As0;
        __nv_bfloat16* Bsc = (kc8 & 1) ? Bs1 : Bs0;
        if (kc8 < 7) {
            __nv_bfloat16* Asn = (kc8 & 1) ? As0 : As1;
            __nv_bfloat16* Bsn = (kc8 & 1) ? Bs0 : Bs1;
            g0_load(g_normed, g_wqkv, Asn, Bsn, m0, n0, (kc8 + 1) * 64, t);
            CP_COMMIT();
            CP_WAIT(1);
        } else {
            CP_WAIT(0);
        }
        __syncthreads();
        unsigned abase = (unsigned)__cvta_generic_to_shared(Asc) + 32 * wm * (G0_ASTR * 2) + lm;
        unsigned bbase = (unsigned)__cvta_generic_to_shared(Bsc) + 64 * wn * 2 + lmB;
        #pragma unroll
        for (int kc = 0; kc < 4; kc++) {
            unsigned a[2][4];
            ldsm4(a[0], abase + kc * 32);
            ldsm4(a[1], abase + 16 * (G0_ASTR * 2) + kc * 32);
            #pragma unroll
            for (int np = 0; np < 4; np++) {
                unsigned b8[4];
                ldsm4t(b8, bbase + kc * 16 * (G0_BSTR * 2) + np * 32);
                mma_bf16(acc[0][2 * np],     a[0][0], a[0][1], a[0][2], a[0][3], b8[0], b8[1]);
                mma_bf16(acc[0][2 * np + 1], a[0][0], a[0][1], a[0][2], a[0][3], b8[2], b8[3]);
                mma_bf16(acc[1][2 * np],     a[1][0], a[1][1], a[1][2], a[1][3], b8[0], b8[1]);
                mma_bf16(acc[1][2 * np + 1], a[1][0], a[1][1], a[1][2], a[1][3], b8[2], b8[3]);
            }
        }
        __syncthreads();
    }

    const float QS = 0.125f * 1.4426950408889634f;
    #pragma unroll
    for (int mt = 0; mt < 2; mt++) {
        #pragma unroll
        for (int rr = 0; rr < 2; rr++) {
            int row = m0 + 32 * wm + 16 * mt + g + 8 * rr;
            #pragma unroll
            for (int nt = 0; nt < 8; nt++) {
                int col = n0 + 64 * wn + 8 * nt + 2 * tq;
                float x0 = acc[mt][nt][2 * rr + 0];
                float x1 = acc[mt][nt][2 * rr + 1];
                if (col < 512) {          // Q: fold softmax scale
                    *(unsigned*)&g_qk[(size_t)row * 1024 + col] = pack_bf16(x0 * QS, x1 * QS);
                } else if (col < 1024) {  // K
                    *(unsigned*)&g_qk[(size_t)row * 1024 + col] = pack_bf16(x0, x1);
                } else {                  // V transposed [b][d][token]
                    int d = col - 1024, bb = row >> 11, tok = row & 2047;
                    g_vT[((size_t)bb * INNER + d)     * MM + tok] = __float2bfloat16(x0);
                    g_vT[((size_t)bb * INNER + d + 1) * MM + tok] = __float2bfloat16(x1);
                }
            }
        }
    }
}

// ---------------------------------------------------------------- bf16 GEMM1: 128x64, k-chunk 64
// g_outpre @ g_wout + bias, GELU, + residual -> out (fp32)
#define G1_ASTR 72
#define G1_BSTR 72
__device__ __forceinline__ void g1_load(const __nv_bfloat16* __restrict__ A,
                                        const __nv_bfloat16* __restrict__ B,
                                        __nv_bfloat16* Asd, __nv_bfloat16* Bsd,
                                        int m0, int n0, int k0, int t) {
    #pragma unroll
    for (int i = 0; i < 4; i++) {           // A: 128 x 64
        int lin = t + i * 256;
        int r = lin >> 3, seg = (lin & 7) * 8;
        cp16(&Asd[r * G1_ASTR + seg], &A[(size_t)(m0 + r) * DIMF + k0 + seg]);
    }
    #pragma unroll
    for (int i = 0; i < 2; i++) {           // B: 64 x 64
        int lin = t + i * 256;
        int r = lin >> 3, seg = (lin & 7) * 8;
        cp16(&Bsd[r * G1_BSTR + seg], &B[(size_t)(k0 + r) * DIMF + n0 + seg]);
    }
}

__global__ __launch_bounds__(256, 2) void gemm1_bf16(const float* __restrict__ bias,
                                                     const float* __restrict__ resid,
                                                     float* __restrict__ C) {
    extern __shared__ __nv_bfloat16 smb[];
    __nv_bfloat16* As0 = smb;
    __nv_bfloat16* As1 = As0 + 128 * G1_ASTR;
    __nv_bfloat16* Bs0 = As1 + 128 * G1_ASTR;
    __nv_bfloat16* Bs1 = Bs0 + 64 * G1_BSTR;

    int m0 = blockIdx.y * 128, n0 = blockIdx.x * 64;
    int t = threadIdx.x;
    int w = t >> 5, lane = t & 31;
    int wm = w >> 1, wn = w & 1;            // warp tile 32x32
    int g = lane >> 2, tq = lane & 3;
    unsigned lm = (lane & 15) * (G1_ASTR * 2) + (lane >> 4) * 16;
    unsigned lmB = (lane & 15) * (G1_BSTR * 2) + (lane >> 4) * 16;

    float acc[2][4][4] = {};

    g1_load(g_outpre, g_wout, As0, Bs0, m0, n0, 0, t);
    CP_COMMIT();

    for (int kc8 = 0; kc8 < 8; kc8++) {
        __nv_bfloat16* Asc = (kc8 & 1) ? As1 : As0;
        __nv_bfloat16* Bsc = (kc8 & 1) ? Bs1 : Bs0;
        if (kc8 < 7) {
            __nv_bfloat16* Asn = (kc8 & 1) ? As0 : As1;
            __nv_bfloat16* Bsn = (kc8 & 1) ? Bs0 : Bs1;
            g1_load(g_outpre, g_wout, Asn, Bsn, m0, n0, (kc8 + 1) * 64, t);
            CP_COMMIT();
            CP_WAIT(1);
        } else {
            CP_WAIT(0);
        }
        __syncthreads();
        unsigned abase = (unsigned)__cvta_generic_to_shared(Asc) + 32 * wm * (G1_ASTR * 2) + lm;
        unsigned bbase = (unsigned)__cvta_generic_to_shared(Bsc) + 32 * wn * 2 + lmB;
        #pragma unroll
        for (int kc = 0; kc < 4; kc++) {
            unsigned a[2][4];
            ldsm4(a[0], abase + kc * 32);
            ldsm4(a[1], abase + 16 * (G1_ASTR * 2) + kc * 32);
            #pragma unroll
            for (int np = 0; np < 2; np++) {
                unsigned b8[4];
                ldsm4t(b8, bbase + kc * 16 * (G1_BSTR * 2) + np * 32);
                mma_bf16(acc[0][2 * np],     a[0][0], a[0][1], a[0][2], a[0][3], b8[0], b8[1]);
                mma_bf16(acc[0][2 * np + 1], a[0][0], a[0][1], a[0][2], a[0][3], b8[2], b8[3]);
                mma_bf16(acc[1][2 * np],     a[1][0], a[1][1], a[1][2], a[1][3], b8[0], b8[1]);
                mma_bf16(acc[1][2 * np + 1], a[1][0], a[1][1], a[1][2], a[1][3], b8[2], b8[3]);
            }
        }
        __syncthreads();
    }

    #pragma unroll
    for (int mt = 0; mt < 2; mt++) {
        #pragma unroll
        for (int rr = 0; rr < 2; rr++) {
            int row = m0 + 32 * wm + 16 * mt + g + 8 * rr;
            #pragma unroll
            for (int nt = 0; nt < 4; nt++) {
                int col = n0 + 32 * wn + 8 * nt + 2 * tq;
                float x0 = acc[mt][nt][2 * rr + 0] + bias[col];
                float x1 = acc[mt][nt][2 * rr + 1] + bias[col + 1];
                x0 = 0.5f * x0 * (1.0f + erff(x0 * 0.70710678118654752f));
                x1 = 0.5f * x1 * (1.0f + erff(x1 * 0.70710678118654752f));
                x0 += resid[(size_t)row * DIMF + col];
                x1 += resid[(size_t)row * DIMF + col + 1];
                *(float2*)&C[(size_t)row * DIMF + col] = make_float2(x0, x1);
            }
        }
    }
}

// ---------------------------------------------------------------- bf16 flash attention + xyz agg
#define KST 72
#define VST 72
#define ATTN_SMEM ((2*64*KST + 2*72*VST) * 2)

__device__ __forceinline__ void attn_load_stage(const __nv_bfloat16* __restrict__ kg,
                                                const __nv_bfloat16* __restrict__ vg,
                                                const __nv_bfloat16* __restrict__ xg,
                                                int j0, __nv_bfloat16* kb, __nv_bfloat16* vb, int t) {
    #pragma unroll
    for (int u = 0; u < 2; u++) {
        int idx = t + 256 * u;
        int r = idx >> 3, seg = (idx & 7) * 8;
        cp16(&kb[r * KST + seg], kg + (size_t)(j0 + r) * 1024 + seg);
        cp16(&vb[r * VST + seg], vg + (size_t)r * MM + j0 + seg);
    }
    if (t < 24) {
        int c = t >> 3, seg = (t & 7) * 8;
        cp16(&vb[(64 + c) * VST + seg], xg + (size_t)c * MM + j0 + seg);
    }
}

__global__ __launch_bounds__(256, 2) void attn_kernel(const float* __restrict__ xyzs,
                                                      const float* __restrict__ w_sp) {
    extern __shared__ __nv_bfloat16 smb[];
    __nv_bfloat16* kbuf0 = smb;
    __nv_bfloat16* kbuf1 = smb + 64 * KST;
    __nv_bfloat16* vbuf0 = smb + 2 * 64 * KST;
    __nv_bfloat16* vbuf1 = vbuf0 + 72 * VST;

    int bh = blockIdx.y;
    int b = bh >> 3, h = bh & 7;
    int i0 = blockIdx.x * 128;
    int t = threadIdx.x;
    int w = t >> 5, lane = t & 31;
    int g = lane >> 2, tq = lane & 3;

    const __nv_bfloat16* vg = g_vT + ((size_t)b * INNER + h * DHD) * MM;
    const __nv_bfloat16* xg = g_xyzT + (size_t)b * 3 * MM;
    const __nv_bfloat16* kgbase = g_qk + 512 + h * DHD + (size_t)b * MM * 1024;

    for (int i = t; i < 2 * 5 * 64; i += 256) {
        int buf = i / (5 * 64), rr = (i / 64) % 5, cc = i & 63;
        (buf ? vbuf1 : vbuf0)[(67 + rr) * VST + cc] = __float2bfloat16(0.f);
    }

    attn_load_stage(kgbase, vg, xg, 0, kbuf0, vbuf0, t);
    CP_COMMIT();

    unsigned qf[4][4];
    {
        const __nv_bfloat16* q0 = g_qk + (size_t)(b * MM + i0 + 16 * w + g) * 1024 + h * DHD;
        const __nv_bfloat16* q1 = q0 + 8 * 1024;
        #pragma unroll
        for (int kc = 0; kc < 4; kc++) {
            qf[kc][0] = *(const unsigned*)(q0 + 16 * kc + 2 * tq);
            qf[kc][1] = *(const unsigned*)(q1 + 16 * kc + 2 * tq);
            qf[kc][2] = *(const unsigned*)(q0 + 16 * kc + 8 + 2 * tq);
            qf[kc][3] = *(const unsigned*)(q1 + 16 * kc + 8 + 2 * tq);
        }
    }

    float of[9][4] = {};
    float l0 = 0.f, l1 = 0.f;
    unsigned lmbase = (lane & 7) * (KST * 2) + (lane >> 3) * 16;

    for (int jt = 0; jt < 32; jt++) {
        __nv_bfloat16* kb = (jt & 1) ? kbuf1 : kbuf0;
        __nv_bfloat16* vb = (jt & 1) ? vbuf1 : vbuf0;
        if (jt < 31) {
            __nv_bfloat16* kn = (jt & 1) ? kbuf0 : kbuf1;
            __nv_bfloat16* vn = (jt & 1) ? vbuf0 : vbuf1;
            attn_load_stage(kgbase, vg, xg, (jt + 1) * 64, kn, vn, t);
            CP_COMMIT();
            CP_WAIT(1);
        } else {
            CP_WAIT(0);
        }
        __syncthreads();

        float sacc[8][4] = {};
        unsigned kaddr = (unsigned)__cvta_generic_to_shared(kb) + lmbase;
        #pragma unroll
        for (int n = 0; n < 8; n++) {
            unsigned b8[8];
            ldsm4(b8,     kaddr);
            ldsm4(b8 + 4, kaddr + 64);
            kaddr += 8 * KST * 2;
            #pragma unroll
            for (int kc = 0; kc < 4; kc++)
                mma_bf16(sacc[n], qf[kc][0], qf[kc][1], qf[kc][2], qf[kc][3],
                         b8[2 * kc], b8[2 * kc + 1]);
        }

        #pragma unroll
        for (int n = 0; n < 8; n++) {
            sacc[n][0] = ex2(sacc[n][0]); sacc[n][1] = ex2(sacc[n][1]);
            sacc[n][2] = ex2(sacc[n][2]); sacc[n][3] = ex2(sacc[n][3]);
            l0 += sacc[n][0] + sacc[n][1];
            l1 += sacc[n][2] + sacc[n][3];
        }

        unsigned pf[4][4];
        #pragma unroll
        for (int kc = 0; kc < 4; kc++) {
            pf[kc][0] = pack_bf16(sacc[2 * kc][0],     sacc[2 * kc][1]);
            pf[kc][1] = pack_bf16(sacc[2 * kc][2],     sacc[2 * kc][3]);
            pf[kc][2] = pack_bf16(sacc[2 * kc + 1][0], sacc[2 * kc + 1][1]);
            pf[kc][3] = pack_bf16(sacc[2 * kc + 1][2], sacc[2 * kc + 1][3]);
        }

        unsigned vaddr = (unsigned)__cvta_generic_to_shared(vb) + lmbase;
        #pragma unroll
        for (int nt = 0; nt < 9; nt++) {
            unsigned v8[8];
            ldsm4(v8,     vaddr);
            ldsm4(v8 + 4, vaddr + 64);
            vaddr += 8 * VST * 2;
            #pragma unroll
            for (int kc = 0; kc < 4; kc++)
                mma_bf16(of[nt], pf[kc][0], pf[kc][1], pf[kc][2], pf[kc][3],
                         v8[2 * kc], v8[2 * kc + 1]);
        }
        __syncthreads();
    }

    #pragma unroll
    for (int o = 1; o < 4; o <<= 1) {
        l0 += __shfl_xor_sync(0xffffffffu, l0, o);
        l1 += __shfl_xor_sync(0xffffffffu, l1, o);
    }

    float invl0 = 1.0f / l0, invl1 = 1.0f / l1;
    int base = lane & ~3;
    float ax0_0 = __shfl_sync(0xffffffffu, of[8][0], base + 0);
    float ax1_0 = __shfl_sync(0xffffffffu, of[8][1], base + 0);
    float ax2_0 = __shfl_sync(0xffffffffu, of[8][0], base + 1);
    float ax0_1 = __shfl_sync(0xffffffffu, of[8][2], base + 0);
    float ax1_1 = __shfl_sync(0xffffffffu, of[8][3], base + 0);
    float ax2_1 = __shfl_sync(0xffffffffu, of[8][2], base + 1);

    int row0 = i0 + 16 * w + g, row1 = row0 + 8;
    const float* xq0 = xyzs + ((size_t)b * MM + row0) * 3;
    const float* xq1 = xyzs + ((size_t)b * MM + row1) * 3;
    float a00 = ax0_0 * invl0 - xq0[0];
    float a10 = ax1_0 * invl0 - xq0[1];
    float a20 = ax2_0 * invl0 - xq0[2];
    float a01 = ax0_1 * invl1 - xq1[0];
    float a11 = ax1_1 * invl1 - xq1[1];
    float a21 = ax2_1 * invl1 - xq1[2];

    __nv_bfloat16* orow0 = g_outpre + ((size_t)b * MM + row0) * INNER + h * DHD;
    __nv_bfloat16* orow1 = g_outpre + ((size_t)b * MM + row1) * INNER + h * DHD;
    #pragma unroll
    for (int n = 0; n < 8; n++) {
        int d = 8 * n + 2 * tq;
        float w00 = w_sp[d],       w01 = w_sp[d + 1];
        float w10 = w_sp[64 + d],  w11 = w_sp[64 + d + 1];
        float w20 = w_sp[128 + d], w21 = w_sp[128 + d + 1];
        float o00 = of[n][0] * invl0 + a00 * w00 + a10 * w10 + a20 * w20;
        float o01 = of[n][1] * invl0 + a00 * w01 + a10 * w11 + a20 * w21;
        float o10 = of[n][2] * invl1 + a01 * w00 + a11 * w10 + a21 * w20;
        float o11 = of[n][3] * invl1 + a01 * w01 + a11 * w11 + a21 * w21;
        *(unsigned*)&orow0[d] = pack_bf16(o00, o01);
        *(unsigned*)&orow1[d] = pack_bf16(o10, o11);
    }
}

// ---------------------------------------------------------------- launch
extern "C" void kernel_launch(void* const* d_in, const int* in_sizes, int n_in,
                              void* d_out, int out_size) {
    const float* xyzs     = (const float*)d_in[0];
    const float* features = (const float*)d_in[1];
    const float* gamma    = (const float*)d_in[2];
    const float* beta     = (const float*)d_in[3];
    const float* w_qkv    = (const float*)d_in[4];
    const float* w_sp     = (const float*)d_in[5];
    const float* w_out    = (const float*)d_in[6];
    const float* b_out    = (const float*)d_in[7];
    float* out = (float*)d_out;

    const int g0_smem = 2 * (128 * G0_ASTR + 64 * G0_BSTR) * 2;   // 71680
    const int g1_smem = 2 * (128 * G1_ASTR + 64 * G1_BSTR) * 2;   // 55296
    cudaFuncSetAttribute(gemm0_bf16, cudaFuncAttributeMaxDynamicSharedMemorySize, g0_smem);
    cudaFuncSetAttribute(gemm1_bf16, cudaFuncAttributeMaxDynamicSharedMemorySize, g1_smem);
    cudaFuncSetAttribute(attn_kernel, cudaFuncAttributeMaxDynamicSharedMemorySize, ATTN_SMEM);

    ln_kernel<<<ROWS, 256>>>(features, gamma, beta);
    cvt_kernel<<<(DIMF * QKVD + 255) / 256, 256>>>(w_qkv, w_out, xyzs);
    gemm0_bf16<<<dim3(QKVD / 128, ROWS / 128), 256, g0_smem>>>();
    attn_kernel<<<dim3(MM / 128, BB * HEADS), 256, ATTN_SMEM>>>(xyzs, w_sp);
    gemm1_bf16<<<dim3(DIMF / 64, ROWS / 128), 256, g1_smem>>>(b_out, features, out);
}

// round 17
// speedup vs baseline: 2.9217x; 1.0517x over previous
#include <cuda_runtime.h>
#include <cuda_bf16.h>
#include <math.h>

#define BB    2
#define MM    2048
#define DIMF  512
#define HEADS 8
#define DHD   64
#define INNER 512
#define QKVD  1536
#define ROWS  (BB*MM)       // 4096

__device__ __nv_bfloat16 g_normed[ROWS * DIMF];    // LN output, bf16
__device__ __nv_bfloat16 g_outpre[ROWS * INNER];   // attention output, bf16
__device__ __nv_bfloat16 g_wqkv[DIMF * QKVD];
__device__ __nv_bfloat16 g_wout[DIMF * DIMF];
__device__ __nv_bfloat16 g_qk[ROWS * 1024];        // cols 0..511 Q (pre-scaled), 512..1023 K
__device__ __nv_bfloat16 g_vT[BB * INNER * MM];    // [b][d][token]
__device__ __nv_bfloat16 g_xyzT[BB * 3 * MM];      // [b][c][token]

__device__ __forceinline__ void mma_bf16(float c[4],
                                         unsigned a0, unsigned a1, unsigned a2, unsigned a3,
                                         unsigned b0, unsigned b1) {
    asm volatile(
        "mma.sync.aligned.m16n8k16.row.col.f32.bf16.bf16.f32 "
        "{%0,%1,%2,%3}, {%4,%5,%6,%7}, {%8,%9}, {%0,%1,%2,%3};\n"
        : "+f"(c[0]), "+f"(c[1]), "+f"(c[2]), "+f"(c[3])
        : "r"(a0), "r"(a1), "r"(a2), "r"(a3), "r"(b0), "r"(b1));
}
__device__ __forceinline__ void ldsm4(unsigned r[4], unsigned addr) {
    asm volatile("ldmatrix.sync.aligned.m8n8.x4.shared.b16 {%0,%1,%2,%3}, [%4];"
                 : "=r"(r[0]), "=r"(r[1]), "=r"(r[2]), "=r"(r[3]) : "r"(addr));
}
__device__ __forceinline__ void ldsm4t(unsigned r[4], unsigned addr) {
    asm volatile("ldmatrix.sync.aligned.m8n8.x4.trans.shared.b16 {%0,%1,%2,%3}, [%4];"
                 : "=r"(r[0]), "=r"(r[1]), "=r"(r[2]), "=r"(r[3]) : "r"(addr));
}
__device__ __forceinline__ unsigned pack_bf16(float lo, float hi) {
    unsigned r; asm("cvt.rn.bf16x2.f32 %0, %1, %2;" : "=r"(r) : "f"(hi), "f"(lo)); return r;
}
__device__ __forceinline__ float ex2(float x) {
    float y; asm("ex2.approx.ftz.f32 %0, %1;" : "=f"(y) : "f"(x)); return y;
}
__device__ __forceinline__ void cp16(void* s, const void* g) {
    unsigned sa = (unsigned)__cvta_generic_to_shared(s);
    asm volatile("cp.async.ca.shared.global [%0], [%1], 16;\n" :: "r"(sa), "l"(g));
}
#define CP_COMMIT() asm volatile("cp.async.commit_group;\n" ::: "memory")
#define CP_WAIT(n)  asm volatile("cp.async.wait_group %0;\n" :: "n"(n) : "memory")

// ---------------------------------------------------------------- LayerNorm: warp per row
__global__ void ln_kernel(const float* __restrict__ x,
                          const float* __restrict__ gamma,
                          const float* __restrict__ beta) {
    int w = threadIdx.x >> 5, lane = threadIdx.x & 31;
    int row = blockIdx.x * 8 + w;
    const float* xr = x + (size_t)row * DIMF;
    float4 v[4];
    float s = 0.f, ss = 0.f;
    #pragma unroll
    for (int i = 0; i < 4; i++) {
        v[i] = *(const float4*)&xr[(lane + 32 * i) * 4];
        s  += v[i].x + v[i].y + v[i].z + v[i].w;
        ss += v[i].x * v[i].x + v[i].y * v[i].y + v[i].z * v[i].z + v[i].w * v[i].w;
    }
    #pragma unroll
    for (int o = 16; o > 0; o >>= 1) {
        s  += __shfl_xor_sync(0xffffffffu, s, o);
        ss += __shfl_xor_sync(0xffffffffu, ss, o);
    }
    float mean = s * (1.0f / DIMF);
    float var  = ss * (1.0f / DIMF) - mean * mean;
    float inv  = rsqrtf(var + 1e-5f);
    __nv_bfloat16* o = g_normed + (size_t)row * DIMF;
    #pragma unroll
    for (int i = 0; i < 4; i++) {
        int c = (lane + 32 * i) * 4;
        float4 gm = *(const float4*)&gamma[c];
        float4 bt = *(const float4*)&beta[c];
        unsigned lo = pack_bf16((v[i].x - mean) * inv * gm.x + bt.x,
                                (v[i].y - mean) * inv * gm.y + bt.y);
        unsigned hi = pack_bf16((v[i].z - mean) * inv * gm.z + bt.z,
                                (v[i].w - mean) * inv * gm.w + bt.w);
        *(uint2*)&o[c] = make_uint2(lo, hi);
    }
}

// ---------------------------------------------------------------- weight + xyz conversion
__global__ void cvt_kernel(const float* __restrict__ wqkv,
                           const float* __restrict__ wout,
                           const float* __restrict__ xyzs) {
    int i = blockIdx.x * 256 + threadIdx.x;
    if (i < DIMF * QKVD) g_wqkv[i] = __float2bfloat16(wqkv[i]);
    if (i < DIMF * DIMF) g_wout[i] = __float2bfloat16(wout[i]);
    if (i < BB * 3 * MM) {
        int b = i / (3 * MM), r = i % (3 * MM);
        int c = r / MM, m = r % MM;
        g_xyzT[i] = __float2bfloat16(xyzs[((size_t)b * MM + m) * 3 + c]);
    }
}

// ---------------------------------------------------------------- bf16 GEMM0: 128x128, k-chunk 64
#define G0_ASTR 72
#define G0_BSTR 136
__device__ __forceinline__ void g0_load(const __nv_bfloat16* __restrict__ A,
                                        const __nv_bfloat16* __restrict__ B,
                                        __nv_bfloat16* Asd, __nv_bfloat16* Bsd,
                                        int m0, int n0, int k0, int t) {
    #pragma unroll
    for (int i = 0; i < 4; i++) {
        int lin = t + i * 256;
        int r = lin >> 3, seg = (lin & 7) * 8;
        cp16(&Asd[r * G0_ASTR + seg], &A[(size_t)(m0 + r) * DIMF + k0 + seg]);
    }
    #pragma unroll
    for (int i = 0; i < 4; i++) {
        int lin = t + i * 256;
        int r = lin >> 4, seg = (lin & 15) * 8;
        cp16(&Bsd[r * G0_BSTR + seg], &B[(size_t)(k0 + r) * QKVD + n0 + seg]);
    }
}

__global__ __launch_bounds__(256, 2) void gemm0_bf16() {
    extern __shared__ __nv_bfloat16 smb[];
    __nv_bfloat16* As0 = smb;
    __nv_bfloat16* As1 = As0 + 128 * G0_ASTR;
    __nv_bfloat16* Bs0 = As1 + 128 * G0_ASTR;
    __nv_bfloat16* Bs1 = Bs0 + 64 * G0_BSTR;

    int m0 = blockIdx.y * 128, n0 = blockIdx.x * 128;
    int t = threadIdx.x;
    int w = t >> 5, lane = t & 31;
    int wm = w >> 1, wn = w & 1;            // warp tile 32x64
    int g = lane >> 2, tq = lane & 3;
    unsigned lm = (lane & 15) * (G0_ASTR * 2) + (lane >> 4) * 16;
    unsigned lmB = (lane & 15) * (G0_BSTR * 2) + (lane >> 4) * 16;

    float acc[2][8][4] = {};

    g0_load(g_normed, g_wqkv, As0, Bs0, m0, n0, 0, t);
    CP_COMMIT();

    for (int kc8 = 0; kc8 < 8; kc8++) {
        __nv_bfloat16* Asc = (kc8 & 1) ? As1 : As0;
        __nv_bfloat16* Bsc = (kc8 & 1) ? Bs1 : Bs0;
        CP_WAIT(0);
        __syncthreads();
        if (kc8 < 7) {
            __nv_bfloat16* Asn = (kc8 & 1) ? As0 : As1;
            __nv_bfloat16* Bsn = (kc8 & 1) ? Bs0 : Bs1;
            g0_load(g_normed, g_wqkv, Asn, Bsn, m0, n0, (kc8 + 1) * 64, t);
            CP_COMMIT();
        }
        unsigned abase = (unsigned)__cvta_generic_to_shared(Asc) + 32 * wm * (G0_ASTR * 2) + lm;
        unsigned bbase = (unsigned)__cvta_generic_to_shared(Bsc) + 64 * wn * 2 + lmB;
        #pragma unroll
        for (int kc = 0; kc < 4; kc++) {
            unsigned a[2][4];
            ldsm4(a[0], abase + kc * 32);
            ldsm4(a[1], abase + 16 * (G0_ASTR * 2) + kc * 32);
            #pragma unroll
            for (int np = 0; np < 4; np++) {
                unsigned b8[4];
                ldsm4t(b8, bbase + kc * 16 * (G0_BSTR * 2) + np * 32);
                mma_bf16(acc[0][2 * np],     a[0][0], a[0][1], a[0][2], a[0][3], b8[0], b8[1]);
                mma_bf16(acc[0][2 * np + 1], a[0][0], a[0][1], a[0][2], a[0][3], b8[2], b8[3]);
                mma_bf16(acc[1][2 * np],     a[1][0], a[1][1], a[1][2], a[1][3], b8[0], b8[1]);
                mma_bf16(acc[1][2 * np + 1], a[1][0], a[1][1], a[1][2], a[1][3], b8[2], b8[3]);
            }
        }
    }

    const float QS = 0.125f * 1.4426950408889634f;
    #pragma unroll
    for (int mt = 0; mt < 2; mt++) {
        #pragma unroll
        for (int rr = 0; rr < 2; rr++) {
            int row = m0 + 32 * wm + 16 * mt + g + 8 * rr;
            #pragma unroll
            for (int nt = 0; nt < 8; nt++) {
                int col = n0 + 64 * wn + 8 * nt + 2 * tq;
                float x0 = acc[mt][nt][2 * rr + 0];
                float x1 = acc[mt][nt][2 * rr + 1];
                if (col < 512) {
                    *(unsigned*)&g_qk[(size_t)row * 1024 + col] = pack_bf16(x0 * QS, x1 * QS);
                } else if (col < 1024) {
                    *(unsigned*)&g_qk[(size_t)row * 1024 + col] = pack_bf16(x0, x1);
                } else {
                    int d = col - 1024, bb = row >> 11, tok = row & 2047;
                    g_vT[((size_t)bb * INNER + d)     * MM + tok] = __float2bfloat16(x0);
                    g_vT[((size_t)bb * INNER + d + 1) * MM + tok] = __float2bfloat16(x1);
                }
            }
        }
    }
}

// ---------------------------------------------------------------- bf16 GEMM1: 128x64, k-chunk 64
#define G1_ASTR 72
#define G1_BSTR 72
__device__ __forceinline__ void g1_load(const __nv_bfloat16* __restrict__ A,
                                        const __nv_bfloat16* __restrict__ B,
                                        __nv_bfloat16* Asd, __nv_bfloat16* Bsd,
                                        int m0, int n0, int k0, int t) {
    #pragma unroll
    for (int i = 0; i < 4; i++) {
        int lin = t + i * 256;
        int r = lin >> 3, seg = (lin & 7) * 8;
        cp16(&Asd[r * G1_ASTR + seg], &A[(size_t)(m0 + r) * DIMF + k0 + seg]);
    }
    #pragma unroll
    for (int i = 0; i < 2; i++) {
        int lin = t + i * 256;
        int r = lin >> 3, seg = (lin & 7) * 8;
        cp16(&Bsd[r * G1_BSTR + seg], &B[(size_t)(k0 + r) * DIMF + n0 + seg]);
    }
}

__global__ __launch_bounds__(256, 2) void gemm1_bf16(const float* __restrict__ bias,
                                                     const float* __restrict__ resid,
                                                     float* __restrict__ C) {
    extern __shared__ __nv_bfloat16 smb[];
    __nv_bfloat16* As0 = smb;
    __nv_bfloat16* As1 = As0 + 128 * G1_ASTR;
    __nv_bfloat16* Bs0 = As1 + 128 * G1_ASTR;
    __nv_bfloat16* Bs1 = Bs0 + 64 * G1_BSTR;

    int m0 = blockIdx.y * 128, n0 = blockIdx.x * 64;
    int t = threadIdx.x;
    int w = t >> 5, lane = t & 31;
    int wm = w >> 1, wn = w & 1;            // warp tile 32x32
    int g = lane >> 2, tq = lane & 3;
    unsigned lm = (lane & 15) * (G1_ASTR * 2) + (lane >> 4) * 16;
    unsigned lmB = (lane & 15) * (G1_BSTR * 2) + (lane >> 4) * 16;

    float acc[2][4][4] = {};

    g1_load(g_outpre, g_wout, As0, Bs0, m0, n0, 0, t);
    CP_COMMIT();

    for (int kc8 = 0; kc8 < 8; kc8++) {
        __nv_bfloat16* Asc = (kc8 & 1) ? As1 : As0;
        __nv_bfloat16* Bsc = (kc8 & 1) ? Bs1 : Bs0;
        CP_WAIT(0);
        __syncthreads();
        if (kc8 < 7) {
            __nv_bfloat16* Asn = (kc8 & 1) ? As0 : As1;
            __nv_bfloat16* Bsn = (kc8 & 1) ? Bs0 : Bs1;
            g1_load(g_outpre, g_wout, Asn, Bsn, m0, n0, (kc8 + 1) * 64, t);
            CP_COMMIT();
        }
        unsigned abase = (unsigned)__cvta_generic_to_shared(Asc) + 32 * wm * (G1_ASTR * 2) + lm;
        unsigned bbase = (unsigned)__cvta_generic_to_shared(Bsc) + 32 * wn * 2 + lmB;
        #pragma unroll
        for (int kc = 0; kc < 4; kc++) {
            unsigned a[2][4];
            ldsm4(a[0], abase + kc * 32);
            ldsm4(a[1], abase + 16 * (G1_ASTR * 2) + kc * 32);
            #pragma unroll
            for (int np = 0; np < 2; np++) {
                unsigned b8[4];
                ldsm4t(b8, bbase + kc * 16 * (G1_BSTR * 2) + np * 32);
                mma_bf16(acc[0][2 * np],     a[0][0], a[0][1], a[0][2], a[0][3], b8[0], b8[1]);
                mma_bf16(acc[0][2 * np + 1], a[0][0], a[0][1], a[0][2], a[0][3], b8[2], b8[3]);
                mma_bf16(acc[1][2 * np],     a[1][0], a[1][1], a[1][2], a[1][3], b8[0], b8[1]);
                mma_bf16(acc[1][2 * np + 1], a[1][0], a[1][1], a[1][2], a[1][3], b8[2], b8[3]);
            }
        }
    }

    #pragma unroll
    for (int mt = 0; mt < 2; mt++) {
        #pragma unroll
        for (int rr = 0; rr < 2; rr++) {
            int row = m0 + 32 * wm + 16 * mt + g + 8 * rr;
            #pragma unroll
            for (int nt = 0; nt < 4; nt++) {
                int col = n0 + 32 * wn + 8 * nt + 2 * tq;
                float x0 = acc[mt][nt][2 * rr + 0] + bias[col];
                float x1 = acc[mt][nt][2 * rr + 1] + bias[col + 1];
                x0 = 0.5f * x0 * (1.0f + erff(x0 * 0.70710678118654752f));
                x1 = 0.5f * x1 * (1.0f + erff(x1 * 0.70710678118654752f));
                x0 += resid[(size_t)row * DIMF + col];
                x1 += resid[(size_t)row * DIMF + col + 1];
                *(float2*)&C[(size_t)row * DIMF + col] = make_float2(x0, x1);
            }
        }
    }
}

// ---------------------------------------------------------------- bf16 flash attention + xyz agg
#define KST 72
#define VST 72
#define ATTN_SMEM ((2*64*KST + 2*72*VST) * 2)

__device__ __forceinline__ void attn_load_stage(const __nv_bfloat16* __restrict__ kg,
                                                const __nv_bfloat16* __restrict__ vg,
                                                const __nv_bfloat16* __restrict__ xg,
                                                int j0, __nv_bfloat16* kb, __nv_bfloat16* vb, int t) {
    #pragma unroll
    for (int u = 0; u < 2; u++) {
        int idx = t + 256 * u;
        int r = idx >> 3, seg = (idx & 7) * 8;
        cp16(&kb[r * KST + seg], kg + (size_t)(j0 + r) * 1024 + seg);
        cp16(&vb[r * VST + seg], vg + (size_t)r * MM + j0 + seg);
    }
    if (t < 24) {
        int c = t >> 3, seg = (t & 7) * 8;
        cp16(&vb[(64 + c) * VST + seg], xg + (size_t)c * MM + j0 + seg);
    }
}

__global__ __launch_bounds__(256, 2) void attn_kernel(const float* __restrict__ xyzs,
                                                      const float* __restrict__ w_sp) {
    extern __shared__ __nv_bfloat16 smb[];
    __nv_bfloat16* kbuf0 = smb;
    __nv_bfloat16* kbuf1 = smb + 64 * KST;
    __nv_bfloat16* vbuf0 = smb + 2 * 64 * KST;
    __nv_bfloat16* vbuf1 = vbuf0 + 72 * VST;

    int bh = blockIdx.y;
    int b = bh >> 3, h = bh & 7;
    int i0 = blockIdx.x * 128;
    int t = threadIdx.x;
    int w = t >> 5, lane = t & 31;
    int g = lane >> 2, tq = lane & 3;

    const __nv_bfloat16* vg = g_vT + ((size_t)b * INNER + h * DHD) * MM;
    const __nv_bfloat16* xg = g_xyzT + (size_t)b * 3 * MM;
    const __nv_bfloat16* kgbase = g_qk + 512 + h * DHD + (size_t)b * MM * 1024;

    for (int i = t; i < 2 * 5 * 64; i += 256) {
        int buf = i / (5 * 64), rr = (i / 64) % 5, cc = i & 63;
        (buf ? vbuf1 : vbuf0)[(67 + rr) * VST + cc] = __float2bfloat16(0.f);
    }

    attn_load_stage(kgbase, vg, xg, 0, kbuf0, vbuf0, t);
    CP_COMMIT();

    unsigned qf[4][4];
    {
        const __nv_bfloat16* q0 = g_qk + (size_t)(b * MM + i0 + 16 * w + g) * 1024 + h * DHD;
        const __nv_bfloat16* q1 = q0 + 8 * 1024;
        #pragma unroll
        for (int kc = 0; kc < 4; kc++) {
            qf[kc][0] = *(const unsigned*)(q0 + 16 * kc + 2 * tq);
            qf[kc][1] = *(const unsigned*)(q1 + 16 * kc + 2 * tq);
            qf[kc][2] = *(const unsigned*)(q0 + 16 * kc + 8 + 2 * tq);
            qf[kc][3] = *(const unsigned*)(q1 + 16 * kc + 8 + 2 * tq);
        }
    }

    float of[9][4] = {};
    float l0 = 0.f, l1 = 0.f;
    unsigned lmbase = (lane & 7) * (KST * 2) + (lane >> 3) * 16;

    for (int jt = 0; jt < 32; jt++) {
        __nv_bfloat16* kb = (jt & 1) ? kbuf1 : kbuf0;
        __nv_bfloat16* vb = (jt & 1) ? vbuf1 : vbuf0;
        CP_WAIT(0);
        __syncthreads();
        if (jt < 31) {
            __nv_bfloat16* kn = (jt & 1) ? kbuf0 : kbuf1;
            __nv_bfloat16* vn = (jt & 1) ? vbuf0 : vbuf1;
            attn_load_stage(kgbase, vg, xg, (jt + 1) * 64, kn, vn, t);
            CP_COMMIT();
        }

        float sacc[8][4] = {};
        unsigned kaddr = (unsigned)__cvta_generic_to_shared(kb) + lmbase;
        #pragma unroll
        for (int n = 0; n < 8; n++) {
            unsigned b8[8];
            ldsm4(b8,     kaddr);
            ldsm4(b8 + 4, kaddr + 64);
            kaddr += 8 * KST * 2;
            #pragma unroll
            for (int kc = 0; kc < 4; kc++)
                mma_bf16(sacc[n], qf[kc][0], qf[kc][1], qf[kc][2], qf[kc][3],
                         b8[2 * kc], b8[2 * kc + 1]);
        }

        #pragma unroll
        for (int n = 0; n < 8; n++) {
            sacc[n][0] = ex2(sacc[n][0]); sacc[n][1] = ex2(sacc[n][1]);
            sacc[n][2] = ex2(sacc[n][2]); sacc[n][3] = ex2(sacc[n][3]);
            l0 += sacc[n][0] + sacc[n][1];
            l1 += sacc[n][2] + sacc[n][3];
        }

        unsigned pf[4][4];
        #pragma unroll
        for (int kc = 0; kc < 4; kc++) {
            pf[kc][0] = pack_bf16(sacc[2 * kc][0],     sacc[2 * kc][1]);
            pf[kc][1] = pack_bf16(sacc[2 * kc][2],     sacc[2 * kc][3]);
            pf[kc][2] = pack_bf16(sacc[2 * kc + 1][0], sacc[2 * kc + 1][1]);
            pf[kc][3] = pack_bf16(sacc[2 * kc + 1][2], sacc[2 * kc + 1][3]);
        }

        unsigned vaddr = (unsigned)__cvta_generic_to_shared(vb) + lmbase;
        #pragma unroll
        for (int nt = 0; nt < 9; nt++) {
            unsigned v8[8];
            ldsm4(v8,     vaddr);
            ldsm4(v8 + 4, vaddr + 64);
            vaddr += 8 * VST * 2;
            #pragma unroll
            for (int kc = 0; kc < 4; kc++)
                mma_bf16(of[nt], pf[kc][0], pf[kc][1], pf[kc][2], pf[kc][3],
                         v8[2 * kc], v8[2 * kc + 1]);
        }
    }

    #pragma unroll
    for (int o = 1; o < 4; o <<= 1) {
        l0 += __shfl_xor_sync(0xffffffffu, l0, o);
        l1 += __shfl_xor_sync(0xffffffffu, l1, o);
    }

    float invl0 = 1.0f / l0, invl1 = 1.0f / l1;
    int base = lane & ~3;
    float ax0_0 = __shfl_sync(0xffffffffu, of[8][0], base + 0);
    float ax1_0 = __shfl_sync(0xffffffffu, of[8][1], base + 0);
    float ax2_0 = __shfl_sync(0xffffffffu, of[8][0], base + 1);
    float ax0_1 = __shfl_sync(0xffffffffu, of[8][2], base + 0);
    float ax1_1 = __shfl_sync(0xffffffffu, of[8][3], base + 0);
    float ax2_1 = __shfl_sync(0xffffffffu, of[8][2], base + 1);

    int row0 = i0 + 16 * w + g, row1 = row0 + 8;
    const float* xq0 = xyzs + ((size_t)b * MM + row0) * 3;
    const float* xq1 = xyzs + ((size_t)b * MM + row1) * 3;
    float a00 = ax0_0 * invl0 - xq0[0];
    float a10 = ax1_0 * invl0 - xq0[1];
    float a20 = ax2_0 * invl0 - xq0[2];
    float a01 = ax0_1 * invl1 - xq1[0];
    float a11 = ax1_1 * invl1 - xq1[1];
    float a21 = ax2_1 * invl1 - xq1[2];

    __nv_bfloat16* orow0 = g_outpre + ((size_t)b * MM + row0) * INNER + h * DHD;
    __nv_bfloat16* orow1 = g_outpre + ((size_t)b * MM + row1) * INNER + h * DHD;
    #pragma unroll
    for (int n = 0; n < 8; n++) {
        int d = 8 * n + 2 * tq;
        float w00 = w_sp[d],       w01 = w_sp[d + 1];
        float w10 = w_sp[64 + d],  w11 = w_sp[64 + d + 1];
        float w20 = w_sp[128 + d], w21 = w_sp[128 + d + 1];
        float o00 = of[n][0] * invl0 + a00 * w00 + a10 * w10 + a20 * w20;
        float o01 = of[n][1] * invl0 + a00 * w01 + a10 * w11 + a20 * w21;
        float o10 = of[n][2] * invl1 + a01 * w00 + a11 * w10 + a21 * w20;
        float o11 = of[n][3] * invl1 + a01 * w01 + a11 * w11 + a21 * w21;
        *(unsigned*)&orow0[d] = pack_bf16(o00, o01);
        *(unsigned*)&orow1[d] = pack_bf16(o10, o11);
    }
}

// ---------------------------------------------------------------- launch
extern "C" void kernel_launch(void* const* d_in, const int* in_sizes, int n_in,
                              void* d_out, int out_size) {
    const float* xyzs     = (const float*)d_in[0];
    const float* features = (const float*)d_in[1];
    const float* gamma    = (const float*)d_in[2];
    const float* beta     = (const float*)d_in[3];
    const float* w_qkv    = (const float*)d_in[4];
    const float* w_sp     = (const float*)d_in[5];
    const float* w_out    = (const float*)d_in[6];
    const float* b_out    = (const float*)d_in[7];
    float* out = (float*)d_out;

    const int g0_smem = 2 * (128 * G0_ASTR + 64 * G0_BSTR) * 2;   // 71680
    const int g1_smem = 2 * (128 * G1_ASTR + 64 * G1_BSTR) * 2;   // 55296
    cudaFuncSetAttribute(gemm0_bf16, cudaFuncAttributeMaxDynamicSharedMemorySize, g0_smem);
    cudaFuncSetAttribute(gemm1_bf16, cudaFuncAttributeMaxDynamicSharedMemorySize, g1_smem);
    cudaFuncSetAttribute(attn_kernel, cudaFuncAttributeMaxDynamicSharedMemorySize, ATTN_SMEM);

    ln_kernel<<<ROWS / 8, 256>>>(features, gamma, beta);
    cvt_kernel<<<(DIMF * QKVD + 255) / 256, 256>>>(w_qkv, w_out, xyzs);
    gemm0_bf16<<<dim3(QKVD / 128, ROWS / 128), 256, g0_smem>>>();
    attn_kernel<<<dim3(MM / 128, BB * HEADS), 256, ATTN_SMEM>>>(xyzs, w_sp);
    gemm1_bf16<<<dim3(DIMF / 64, ROWS / 128), 256, g1_smem>>>(b_out, features, out);
}